// round 14
// baseline (speedup 1.0000x reference)
#include <cuda_runtime.h>
#include <cuda_bf16.h>
#include <math.h>
#include <stdint.h>

#define BATCH 4
#define C     64
#define H     160
#define W     160
#define HW    (H*W)
#define DG    4
#define KKTAP 9
#define CG    16
#define CO2   108    // 3*DG*KK
#define JDIM  576    // DG*CG*KK
#define NT    128    // k34 pixel tile

// ---- scratch (no cudaMalloc allowed) ----
__device__ float g_com [BATCH * CO2 * HW];       // 3x3 conv output (fp32)
__device__ float g_feaT[BATCH * DG * HW * CG];   // fea NHWC-per-group
__device__ __nv_bfloat16 g_qh [BATCH * HW * 64]; // off_feat NHWC hi
__device__ __nv_bfloat16 g_ql [BATCH * HW * 64]; // off_feat NHWC lo
// w_com A tiles: [half(2)][part(2)][tap(9)][oc(64)][ic 72 padded] bf16
__device__ __nv_bfloat16 g_wA[2 * 2 * 9 * 64 * 72];
// w_dcn A tiles for k34: [chunk 36][part 2][oc 64][k 16] bf16
__device__ __nv_bfloat16 g_wd[36 * 2 * 64 * 16];

// ---------- packed f32x2 helpers ----------
__device__ __forceinline__ unsigned long long pack2(float lo, float hi) {
    unsigned long long r;
    asm("mov.b64 %0, {%1, %2};" : "=l"(r) : "f"(lo), "f"(hi));
    return r;
}
__device__ __forceinline__ void unpack2(unsigned long long v, float& lo, float& hi) {
    asm("mov.b64 {%0, %1}, %2;" : "=f"(lo), "=f"(hi) : "l"(v));
}
__device__ __forceinline__ void fma2(unsigned long long& d,
                                     unsigned long long a,
                                     unsigned long long b) {
    asm("fma.rn.f32x2 %0, %1, %2, %0;" : "+l"(d) : "l"(a), "l"(b));
}

// ---------- mma.sync / ldmatrix helpers ----------
__device__ __forceinline__ uint32_t smem_u32(const void* p) {
    uint32_t a;
    asm("{ .reg .u64 t; cvta.to.shared.u64 t, %1; cvt.u32.u64 %0, t; }"
        : "=r"(a) : "l"(p));
    return a;
}
__device__ __forceinline__ void ldsm_x4(uint32_t& r0, uint32_t& r1,
                                        uint32_t& r2, uint32_t& r3, uint32_t addr) {
    asm volatile("ldmatrix.sync.aligned.m8n8.x4.shared.b16 {%0,%1,%2,%3}, [%4];"
        : "=r"(r0), "=r"(r1), "=r"(r2), "=r"(r3) : "r"(addr));
}
__device__ __forceinline__ void ldsm_x2(uint32_t& r0, uint32_t& r1, uint32_t addr) {
    asm volatile("ldmatrix.sync.aligned.m8n8.x2.shared.b16 {%0,%1}, [%2];"
        : "=r"(r0), "=r"(r1) : "r"(addr));
}
__device__ __forceinline__ void mma16816(float* c,
    uint32_t a0, uint32_t a1, uint32_t a2, uint32_t a3,
    uint32_t b0, uint32_t b1) {
    asm("mma.sync.aligned.m16n8k16.row.col.f32.bf16.bf16.f32 "
        "{%0,%1,%2,%3}, {%4,%5,%6,%7}, {%8,%9}, {%0,%1,%2,%3};"
        : "+f"(c[0]), "+f"(c[1]), "+f"(c[2]), "+f"(c[3])
        : "r"(a0), "r"(a1), "r"(a2), "r"(a3), "r"(b0), "r"(b1));
}

// ============================================================
// K0b: fea NCHW -> NHWC-per-group: g_feaT[b][g][p][c16]
// ============================================================
__global__ __launch_bounds__(256) void k0b_feaT(const float* __restrict__ fea)
{
    __shared__ float s[16][65];
    int t = threadIdx.x;
    int b = blockIdx.z, g = blockIdx.y;
    int base = blockIdx.x * 64;
    #pragma unroll
    for (int r = 0; r < 4; r++) {
        int idx = t + r * 256;
        int c = idx >> 6, p = idx & 63;
        s[c][p] = fea[((size_t)(b * C + g * CG + c)) * HW + base + p];
    }
    __syncthreads();
    int p = t >> 2, q = (t & 3) * 4;
    float4 v = make_float4(s[q][p], s[q+1][p], s[q+2][p], s[q+3][p]);
    *(float4*)(g_feaT + (((size_t)(b * DG + g) * HW) + base + p) * CG + q) = v;
}

// ============================================================
// K0c: w_com -> bf16 hi/lo A tiles [half][part][tap][oc64][72]
// ============================================================
__global__ __launch_bounds__(256) void k0c_wA(const float* __restrict__ w_com)
{
    int idx = blockIdx.x * 256 + threadIdx.x;
    if (idx >= 2 * 2 * 9 * 64 * 72) return;
    int ic = idx % 72;
    int r  = idx / 72;
    int oc = r & 63;
    int r2 = r >> 6;
    int tap = r2 % 9;
    int hp  = r2 / 9;
    int part = hp & 1, half = hp >> 1;
    int ocg = half * 64 + oc;
    float v = (ocg < CO2 && ic < 64)
            ? w_com[(size_t)ocg * (C * 9) + ic * 9 + tap] : 0.f;
    __nv_bfloat16 h = __float2bfloat16(v);
    __nv_bfloat16 l = __float2bfloat16(v - __bfloat162float(h));
    g_wA[idx] = part ? l : h;
}

// ============================================================
// K0d: w_dcn -> bf16 hi/lo chunk tiles [gk 36][part 2][oc 64][k 16]
// ============================================================
__global__ __launch_bounds__(256) void k0d_wd(const float* __restrict__ w_dcn)
{
    int idx = blockIdx.x * 256 + threadIdx.x;
    if (idx >= 36 * 2 * 64 * 16) return;
    int kk   = idx & 15;
    int oc   = (idx >> 4) & 63;
    int part = (idx >> 10) & 1;
    int gk   = idx >> 11;
    int g = gk / 9, k = gk - 9 * g;
    float v = w_dcn[(size_t)oc * JDIM + (g * CG + kk) * KKTAP + k];
    __nv_bfloat16 h = __float2bfloat16(v);
    __nv_bfloat16 l = __float2bfloat16(v - __bfloat162float(h));
    g_wd[idx] = part ? l : h;
}

// ============================================================
// K1: off_feat = BN(fea @ w_off) -> NHWC bf16 hi/lo (MLP=8)
// ============================================================
__global__ __launch_bounds__(256, 2) void k1_pointwise(
    const float* __restrict__ fea, const float* __restrict__ w_off,
    const float* __restrict__ gamma, const float* __restrict__ beta,
    const float* __restrict__ mean, const float* __restrict__ var)
{
    __shared__ float ws[64 * 64];
    __shared__ float sc[64], sh[64];
    int t = threadIdx.x;
    for (int idx = t; idx < 4096; idx += 256) {
        int o = idx & 63, i = idx >> 6;
        ws[i * 64 + o] = w_off[o * 64 + i];
    }
    if (t < 64) {
        float inv = gamma[t] * rsqrtf(var[t] + 1e-5f);
        sc[t] = inv;
        sh[t] = beta[t] - mean[t] * inv;
    }
    __syncthreads();

    int b = blockIdx.y;
    int p = blockIdx.x * 256 + t;
    const float* fb = fea + (size_t)b * C * HW + p;

    unsigned long long acc[32];
    #pragma unroll
    for (int o = 0; o < 32; o++) acc[o] = 0ull;

    #pragma unroll
    for (int i0 = 0; i0 < 64; i0 += 8) {
        float a[8];
        #pragma unroll
        for (int j = 0; j < 8; j++)
            a[j] = fb[(size_t)(i0 + j) * HW];
        #pragma unroll
        for (int j = 0; j < 8; j++) {
            unsigned long long a2 = pack2(a[j], a[j]);
            const ulonglong2* w2 = (const ulonglong2*)(ws + (i0 + j) * 64);
            #pragma unroll
            for (int o4 = 0; o4 < 16; o4++) {
                ulonglong2 w = w2[o4];
                fma2(acc[2*o4+0], a2, w.x);
                fma2(acc[2*o4+1], a2, w.y);
            }
        }
    }

    uint4* dh = (uint4*)(g_qh + ((size_t)(b * HW) + p) * 64);
    uint4* dl = (uint4*)(g_ql + ((size_t)(b * HW) + p) * 64);
    #pragma unroll
    for (int j = 0; j < 8; j++) {
        unsigned int hv[4], lv[4];
        #pragma unroll
        for (int q = 0; q < 4; q++) {
            int o = 4 * j + q;
            float v0, v1;
            unpack2(acc[o], v0, v1);
            v0 = v0 * sc[2*o]   + sh[2*o];
            v1 = v1 * sc[2*o+1] + sh[2*o+1];
            __nv_bfloat16 h0 = __float2bfloat16(v0);
            __nv_bfloat16 l0 = __float2bfloat16(v0 - __bfloat162float(h0));
            __nv_bfloat16 h1 = __float2bfloat16(v1);
            __nv_bfloat16 l1 = __float2bfloat16(v1 - __bfloat162float(h1));
            hv[q] = (unsigned)__bfloat16_as_ushort(h0) |
                    ((unsigned)__bfloat16_as_ushort(h1) << 16);
            lv[q] = (unsigned)__bfloat16_as_ushort(l0) |
                    ((unsigned)__bfloat16_as_ushort(l1) << 16);
        }
        dh[j] = make_uint4(hv[0], hv[1], hv[2], hv[3]);
        dl[j] = make_uint4(lv[0], lv[1], lv[2], lv[3]);
    }
}

// ============================================================
// K2_MMA: conv3x3 via mma.sync bf16 3-split (unchanged).
// ============================================================
#define K2_A_PART  82944
#define K2_B_OFF   165888
#define K2_B_PART  25920
#define K2_SMEM    217728

__global__ __launch_bounds__(256) void k2_mma(const float* __restrict__ b_com)
{
    extern __shared__ __align__(16) char sm[];
    uint32_t smb = smem_u32(sm);
    int t    = threadIdx.x;
    int lane = t & 31;
    int wid  = t >> 5;
    int half = blockIdx.y;

    {
        const uint4* gA = (const uint4*)g_wA + (size_t)half * 10368;
        for (int i = t; i < 10368; i += 256)
            *(uint4*)(sm + i * 16) = gA[i];
    }

    int wm = wid & 1;
    int wn = wid >> 1;
    int g  = lane >> 2;
    int tt = lane & 3;

    uint32_t arow = (uint32_t)((wm * 32 + (lane & 15)) * 144 + (lane >> 4) * 16);
    int bln  = lane & 7;
    uint32_t bk16 = (uint32_t)(((lane >> 3) & 1) * 16);

    float bias[2][2];
    bool  bval[2][2];
    #pragma unroll
    for (int mf = 0; mf < 2; mf++)
        #pragma unroll
        for (int rh = 0; rh < 2; rh++) {
            int ocg = half * 64 + wm * 32 + mf * 16 + g + rh * 8;
            bval[mf][rh] = (ocg < CO2);
            bias[mf][rh] = bval[mf][rh] ? b_com[ocg] : 0.f;
        }

    for (int u = blockIdx.x; u < 800; u += 148) {
        int b  = u / 200;
        int rr = u - b * 200;
        int tr = rr / 10, tc = rr - tr * 10;
        int row0 = tr * 8, col0 = tc * 16;

        __syncthreads();

        for (int idx = t; idx < 2880; idx += 256) {
            int q    = idx & 7;
            int rest = idx >> 3;
            int part = rest & 1;
            int pxi  = rest >> 1;
            int hr = pxi / 18, hc = pxi - hr * 18;
            int grw = row0 + hr - 1, gcw = col0 + hc - 1;
            uint4 v = make_uint4(0u, 0u, 0u, 0u);
            if ((unsigned)grw < (unsigned)H && (unsigned)gcw < (unsigned)W) {
                const __nv_bfloat16* srcb = part ? g_ql : g_qh;
                v = ((const uint4*)(srcb +
                      ((size_t)b * HW + (size_t)grw * W + gcw) * 64))[q];
            }
            *(uint4*)(sm + K2_B_OFF + part * K2_B_PART + pxi * 144 + q * 16) = v;
        }
        __syncthreads();

        float acc[2][4][4];
        #pragma unroll
        for (int mf = 0; mf < 2; mf++)
            #pragma unroll
            for (int nf = 0; nf < 4; nf++)
                #pragma unroll
                for (int i = 0; i < 4; i++) acc[mf][nf][i] = 0.f;

        #pragma unroll 1
        for (int tap = 0; tap < 9; tap++) {
            int dy = tap / 3 - 1;
            int dx = tap - (tap / 3) * 3 - 1;
            uint32_t aA = smb + (uint32_t)tap * 9216 + arow;
            int brow_base = (2 * wn + dy + 1) * 18 + (dx + 1) + bln;
            uint32_t bB = smb + K2_B_OFF + bk16;

            #pragma unroll
            for (int ks = 0; ks < 4; ks++) {
                uint32_t ah[2][4], al[2][4];
                #pragma unroll
                for (int mf = 0; mf < 2; mf++) {
                    uint32_t ao = aA + (uint32_t)(mf * 2304 + ks * 32);
                    ldsm_x4(ah[mf][0], ah[mf][1], ah[mf][2], ah[mf][3], ao);
                    ldsm_x4(al[mf][0], al[mf][1], al[mf][2], al[mf][3],
                            ao + K2_A_PART);
                }
                #pragma unroll
                for (int nf = 0; nf < 4; nf++) {
                    int pxrow = brow_base + (nf >> 1) * 18 + (nf & 1) * 8;
                    uint32_t baddr = bB + (uint32_t)(pxrow * 144 + ks * 32);
                    uint32_t bh0, bh1, bl0, bl1;
                    ldsm_x2(bh0, bh1, baddr);
                    ldsm_x2(bl0, bl1, baddr + K2_B_PART);
                    #pragma unroll
                    for (int mf = 0; mf < 2; mf++) {
                        mma16816(acc[mf][nf], ah[mf][0], ah[mf][1], ah[mf][2],
                                 ah[mf][3], bh0, bh1);
                        mma16816(acc[mf][nf], ah[mf][0], ah[mf][1], ah[mf][2],
                                 ah[mf][3], bl0, bl1);
                        mma16816(acc[mf][nf], al[mf][0], al[mf][1], al[mf][2],
                                 al[mf][3], bh0, bh1);
                    }
                }
            }
        }

        #pragma unroll
        for (int mf = 0; mf < 2; mf++) {
            int oc0 = half * 64 + wm * 32 + mf * 16 + g;
            #pragma unroll
            for (int nf = 0; nf < 4; nf++) {
                int srow = row0 + 2 * wn + (nf >> 1);
                int scol = col0 + (nf & 1) * 8 + 2 * tt;
                size_t pbase = (size_t)srow * W + scol;
                if (bval[mf][0]) {
                    float* d = g_com + ((size_t)b * CO2 + oc0) * HW + pbase;
                    d[0] = acc[mf][nf][0] + bias[mf][0];
                    d[1] = acc[mf][nf][1] + bias[mf][0];
                }
                if (bval[mf][1]) {
                    float* d = g_com + ((size_t)b * CO2 + oc0 + 8) * HW + pbase;
                    d[0] = acc[mf][nf][2] + bias[mf][1];
                    d[1] = acc[mf][nf][3] + bias[mf][1];
                }
            }
        }
    }
}

// ============================================================
// K34_MMA: fused sampling + DCN GEMM + relu + residual.
// R13 base + 2-stage com pipeline: the 3 offset/mask scalars for
// chunk gk+2 load while chunk gk is consumed, removing the first
// global-latency hop from the per-chunk critical chain.
// ============================================================
__global__ __launch_bounds__(256) void k34_mma(
    const float* __restrict__ fea, const float* __restrict__ b_dcn,
    float* __restrict__ out)
{
    __shared__ __align__(16) char a_sm[2][2][64 * 48];    // [buf][part]
    __shared__ __align__(16) char b_sm[2][2][128 * 48];   // [buf][part]

    int t    = threadIdx.x;
    int lane = t & 31;
    int wid  = t >> 5;
    int b    = blockIdx.y;
    int n0   = blockIdx.x * NT;

    const float* comb = g_com  + (size_t)b * CO2 * HW;
    const float* ftb  = g_feaT + (size_t)b * DG * HW * CG;

    int pxi   = t & 127;
    int layer = t >> 7;
    int c0    = layer * 8;
    int p     = n0 + pxi;
    int ph    = p / W;
    int pw    = p - ph * W;

    int aw_part = t >> 7;
    int aw_row  = (t >> 1) & 63;
    int aw_half = t & 1;

    int wm = wid & 1;
    int wn = wid >> 1;
    int g  = lane >> 2;
    int tt = lane & 3;
    uint32_t a_lane = (uint32_t)((wm * 32 + (lane & 15)) * 48 + (lane >> 4) * 16);
    uint32_t b_lane = (uint32_t)((lane & 7) * 48 + ((lane >> 3) & 1) * 16);

    uint32_t ab[2][2], bb[2][2];
    #pragma unroll
    for (int bu = 0; bu < 2; bu++)
        #pragma unroll
        for (int pa = 0; pa < 2; pa++) {
            ab[bu][pa] = smem_u32(&a_sm[bu][pa][0]);
            bb[bu][pa] = smem_u32(&b_sm[bu][pa][0]);
        }

    float acc[2][4][4];
    #pragma unroll
    for (int mf = 0; mf < 2; mf++)
        #pragma unroll
        for (int nf = 0; nf < 4; nf++)
            #pragma unroll
            for (int i = 0; i < 4; i++) acc[mf][nf][i] = 0.f;

// com-scalar loader (3 independent LDG.32 + sigmoid); _ prefixed.
#define LOAD_COM(GK, DY, DX, MM)                                              \
    {                                                                         \
        int _gk = (GK);                                                       \
        int _g = _gk / 9, _k = _gk - 9 * _g;                                  \
        DY = comb[(size_t)(_g*18 + 2*_k    ) * HW + p];                       \
        DX = comb[(size_t)(_g*18 + 2*_k + 1) * HW + p];                       \
        float _m = comb[(size_t)(72 + _g*9 + _k) * HW + p];                   \
        MM = 1.f / (1.f + __expf(-_m));                                       \
    }

// gather + convert + STS, using pre-loaded com scalars.
#define PRODUCE(GK, BUF, DY, DX, MM)                                          \
    {                                                                         \
        int _gk = (GK);                                                       \
        int _buf = (BUF);                                                     \
        int _g = _gk / 9, _k = _gk - 9 * _g;                                  \
        float _py = (DY) + (float)(_k / 3 - 1) + (float)ph;                   \
        float _px = (DX) + (float)(_k % 3 - 1) + (float)pw;                   \
        float _y0f = floorf(_py), _x0f = floorf(_px);                         \
        float _wy = _py - _y0f, _wx = _px - _x0f;                             \
        int _y0 = (int)_y0f, _x0 = (int)_x0f;                                 \
        int _y1 = _y0 + 1,   _x1 = _x0 + 1;                                   \
        bool _vy0 = (_y0 >= 0 && _y0 < H), _vy1 = (_y1 >= 0 && _y1 < H);      \
        bool _vx0 = (_x0 >= 0 && _x0 < W), _vx1 = (_x1 >= 0 && _x1 < W);      \
        float _w00 = (1.f-_wy)*(1.f-_wx) * (float)(_vy0 && _vx0) * (MM);      \
        float _w01 = (1.f-_wy)*_wx       * (float)(_vy0 && _vx1) * (MM);      \
        float _w10 = _wy*(1.f-_wx)       * (float)(_vy1 && _vx0) * (MM);      \
        float _w11 = _wy*_wx             * (float)(_vy1 && _vx1) * (MM);      \
        int _y0c = min(max(_y0, 0), H-1), _y1c = min(max(_y1, 0), H-1);       \
        int _x0c = min(max(_x0, 0), W-1), _x1c = min(max(_x1, 0), W-1);       \
        const float* _fg  = ftb + (size_t)_g * HW * CG;                       \
        const float* _p00 = _fg + (size_t)(_y0c * W + _x0c) * CG + c0;        \
        const float* _p01 = _fg + (size_t)(_y0c * W + _x1c) * CG + c0;        \
        const float* _p10 = _fg + (size_t)(_y1c * W + _x0c) * CG + c0;        \
        const float* _p11 = _fg + (size_t)(_y1c * W + _x1c) * CG + c0;        \
        float4 _a00 = *(const float4*)_p00, _b00 = *(const float4*)(_p00+4);  \
        float4 _a01 = *(const float4*)_p01, _b01 = *(const float4*)(_p01+4);  \
        float4 _a10 = *(const float4*)_p10, _b10 = *(const float4*)(_p10+4);  \
        float4 _a11 = *(const float4*)_p11, _b11 = *(const float4*)(_p11+4);  \
        float _v[8];                                                          \
        _v[0] = _w00*_a00.x+_w01*_a01.x+_w10*_a10.x+_w11*_a11.x;              \
        _v[1] = _w00*_a00.y+_w01*_a01.y+_w10*_a10.y+_w11*_a11.y;              \
        _v[2] = _w00*_a00.z+_w01*_a01.z+_w10*_a10.z+_w11*_a11.z;              \
        _v[3] = _w00*_a00.w+_w01*_a01.w+_w10*_a10.w+_w11*_a11.w;              \
        _v[4] = _w00*_b00.x+_w01*_b01.x+_w10*_b10.x+_w11*_b11.x;              \
        _v[5] = _w00*_b00.y+_w01*_b01.y+_w10*_b10.y+_w11*_b11.y;              \
        _v[6] = _w00*_b00.z+_w01*_b01.z+_w10*_b10.z+_w11*_b11.z;              \
        _v[7] = _w00*_b00.w+_w01*_b01.w+_w10*_b10.w+_w11*_b11.w;              \
        unsigned int _hv[4], _lv[4];                                          \
        _Pragma("unroll")                                                     \
        for (int _q = 0; _q < 4; _q++) {                                      \
            __nv_bfloat16 _h0 = __float2bfloat16(_v[2*_q]);                   \
            __nv_bfloat16 _l0 = __float2bfloat16(_v[2*_q] - __bfloat162float(_h0)); \
            __nv_bfloat16 _h1 = __float2bfloat16(_v[2*_q+1]);                 \
            __nv_bfloat16 _l1 = __float2bfloat16(_v[2*_q+1] - __bfloat162float(_h1)); \
            _hv[_q] = (unsigned)__bfloat16_as_ushort(_h0) |                   \
                      ((unsigned)__bfloat16_as_ushort(_h1) << 16);            \
            _lv[_q] = (unsigned)__bfloat16_as_ushort(_l0) |                   \
                      ((unsigned)__bfloat16_as_ushort(_l1) << 16);            \
        }                                                                     \
        *(uint4*)&b_sm[_buf][0][pxi * 48 + layer * 16] =                      \
            make_uint4(_hv[0], _hv[1], _hv[2], _hv[3]);                       \
        *(uint4*)&b_sm[_buf][1][pxi * 48 + layer * 16] =                      \
            make_uint4(_lv[0], _lv[1], _lv[2], _lv[3]);                       \
        *(uint4*)&a_sm[_buf][aw_part][aw_row * 48 + aw_half * 16] =           \
            *(const uint4*)(g_wd + (((size_t)(_gk * 2 + aw_part) * 64 +       \
                                     aw_row) * 16) + aw_half * 8);            \
    }

    float c_dy, c_dx, c_mm;     // com scalars for next chunk to produce
    float n_dy, n_dx, n_mm;     // com scalars in flight (chunk+1 further)

    LOAD_COM(0, c_dy, c_dx, c_mm)
    PRODUCE(0, 0, c_dy, c_dx, c_mm)
    LOAD_COM(1, c_dy, c_dx, c_mm)
    __syncthreads();

    for (int gk = 0; gk < 36; gk++) {
        int cur = gk & 1;
        if (gk < 34) LOAD_COM(gk + 2, n_dy, n_dx, n_mm)   // in flight during all below
        if (gk < 35) PRODUCE(gk + 1, cur ^ 1, c_dy, c_dx, c_mm)

        uint32_t ah[2][4], al[2][4];
        #pragma unroll
        for (int mf = 0; mf < 2; mf++) {
            uint32_t ao = a_lane + (uint32_t)(mf * 16 * 48);
            ldsm_x4(ah[mf][0], ah[mf][1], ah[mf][2], ah[mf][3], ab[cur][0] + ao);
            ldsm_x4(al[mf][0], al[mf][1], al[mf][2], al[mf][3], ab[cur][1] + ao);
        }
        #pragma unroll
        for (int nf = 0; nf < 4; nf++) {
            uint32_t bo = b_lane + (uint32_t)((wn * 32 + nf * 8) * 48);
            uint32_t bh0, bh1, bl0, bl1;
            ldsm_x2(bh0, bh1, bb[cur][0] + bo);
            ldsm_x2(bl0, bl1, bb[cur][1] + bo);
            #pragma unroll
            for (int mf = 0; mf < 2; mf++) {
                mma16816(acc[mf][nf], ah[mf][0], ah[mf][1], ah[mf][2], ah[mf][3],
                         bh0, bh1);
                mma16816(acc[mf][nf], ah[mf][0], ah[mf][1], ah[mf][2], ah[mf][3],
                         bl0, bl1);
                mma16816(acc[mf][nf], al[mf][0], al[mf][1], al[mf][2], al[mf][3],
                         bh0, bh1);
            }
        }

        c_dy = n_dy; c_dx = n_dx; c_mm = n_mm;
        __syncthreads();
    }
#undef PRODUCE
#undef LOAD_COM

    // ---- epilogue: bias, relu, residual ----
    #pragma unroll
    for (int mf = 0; mf < 2; mf++) {
        int oc0 = wm * 32 + mf * 16 + g;
        float bi0 = b_dcn[oc0];
        float bi1 = b_dcn[oc0 + 8];
        #pragma unroll
        for (int nf = 0; nf < 4; nf++) {
            int pxl = wn * 32 + nf * 8 + 2 * tt;
            size_t b0 = ((size_t)b * C + oc0) * HW + n0 + pxl;
            size_t b1 = ((size_t)b * C + oc0 + 8) * HW + n0 + pxl;
            float2 f0 = *(const float2*)(fea + b0);
            float2 f1 = *(const float2*)(fea + b1);
            float2 o0, o1;
            o0.x = f0.x + fmaxf(acc[mf][nf][0] + bi0, 0.f);
            o0.y = f0.y + fmaxf(acc[mf][nf][1] + bi0, 0.f);
            o1.x = f1.x + fmaxf(acc[mf][nf][2] + bi1, 0.f);
            o1.y = f1.y + fmaxf(acc[mf][nf][3] + bi1, 0.f);
            *(float2*)(out + b0) = o0;
            *(float2*)(out + b1) = o1;
        }
    }
}

// ============================================================
extern "C" void kernel_launch(void* const* d_in, const int* in_sizes, int n_in,
                              void* d_out, int out_size)
{
    const float* fea      = (const float*)d_in[0];
    const float* w_off    = (const float*)d_in[1];
    const float* bn_gamma = (const float*)d_in[2];
    const float* bn_beta  = (const float*)d_in[3];
    const float* bn_mean  = (const float*)d_in[4];
    const float* bn_var   = (const float*)d_in[5];
    const float* w_com    = (const float*)d_in[6];
    const float* b_com    = (const float*)d_in[7];
    const float* w_dcn    = (const float*)d_in[8];
    const float* b_dcn    = (const float*)d_in[9];
    float* out = (float*)d_out;

    cudaFuncSetAttribute(k2_mma, cudaFuncAttributeMaxDynamicSharedMemorySize, K2_SMEM);

    k0b_feaT    <<<dim3(HW/64, DG, BATCH), 256>>>(fea);
    k0c_wA      <<<648, 256>>>(w_com);
    k0d_wd      <<<(36 * 2 * 64 * 16 + 255) / 256, 256>>>(w_dcn);
    k1_pointwise<<<dim3(HW/256, BATCH), 256>>>(fea, w_off, bn_gamma, bn_beta, bn_mean, bn_var);
    k2_mma      <<<dim3(148, 2), 256, K2_SMEM>>>(b_com);
    k34_mma     <<<dim3(HW/NT, BATCH), 256>>>(fea, b_dcn, out);
}

// round 15
// speedup vs baseline: 1.0140x; 1.0140x over previous
#include <cuda_runtime.h>
#include <cuda_bf16.h>
#include <math.h>
#include <stdint.h>

#define BATCH 4
#define C     64
#define H     160
#define W     160
#define HW    (H*W)
#define DG    4
#define KKTAP 9
#define CG    16
#define CO2   108    // 3*DG*KK
#define JDIM  576    // DG*CG*KK
#define NT    128    // k34 pixel tile

// ---- scratch (no cudaMalloc allowed) ----
__device__ float g_com [BATCH * CO2 * HW];       // 3x3 conv output (fp32)
__device__ float g_feaT[BATCH * DG * HW * CG];   // fea NHWC-per-group
__device__ __nv_bfloat16 g_qh [BATCH * HW * 64]; // off_feat NHWC hi
__device__ __nv_bfloat16 g_ql [BATCH * HW * 64]; // off_feat NHWC lo
// w_com A tiles: [half(2)][part(2)][tap(9)][oc(64)][ic 72 padded] bf16
__device__ __nv_bfloat16 g_wA[2 * 2 * 9 * 64 * 72];
// w_dcn A tiles for k34: [chunk 36][part 2][oc 64][k 16] bf16
__device__ __nv_bfloat16 g_wd[36 * 2 * 64 * 16];

// ---------- packed f32x2 helpers ----------
__device__ __forceinline__ unsigned long long pack2(float lo, float hi) {
    unsigned long long r;
    asm("mov.b64 %0, {%1, %2};" : "=l"(r) : "f"(lo), "f"(hi));
    return r;
}
__device__ __forceinline__ void unpack2(unsigned long long v, float& lo, float& hi) {
    asm("mov.b64 {%0, %1}, %2;" : "=f"(lo), "=f"(hi) : "l"(v));
}
__device__ __forceinline__ void fma2(unsigned long long& d,
                                     unsigned long long a,
                                     unsigned long long b) {
    asm("fma.rn.f32x2 %0, %1, %2, %0;" : "+l"(d) : "l"(a), "l"(b));
}

// ---------- mma.sync / ldmatrix helpers ----------
__device__ __forceinline__ uint32_t smem_u32(const void* p) {
    uint32_t a;
    asm("{ .reg .u64 t; cvta.to.shared.u64 t, %1; cvt.u32.u64 %0, t; }"
        : "=r"(a) : "l"(p));
    return a;
}
__device__ __forceinline__ void ldsm_x4(uint32_t& r0, uint32_t& r1,
                                        uint32_t& r2, uint32_t& r3, uint32_t addr) {
    asm volatile("ldmatrix.sync.aligned.m8n8.x4.shared.b16 {%0,%1,%2,%3}, [%4];"
        : "=r"(r0), "=r"(r1), "=r"(r2), "=r"(r3) : "r"(addr));
}
__device__ __forceinline__ void ldsm_x2(uint32_t& r0, uint32_t& r1, uint32_t addr) {
    asm volatile("ldmatrix.sync.aligned.m8n8.x2.shared.b16 {%0,%1}, [%2];"
        : "=r"(r0), "=r"(r1) : "r"(addr));
}
__device__ __forceinline__ void mma16816(float* c,
    uint32_t a0, uint32_t a1, uint32_t a2, uint32_t a3,
    uint32_t b0, uint32_t b1) {
    asm("mma.sync.aligned.m16n8k16.row.col.f32.bf16.bf16.f32 "
        "{%0,%1,%2,%3}, {%4,%5,%6,%7}, {%8,%9}, {%0,%1,%2,%3};"
        : "+f"(c[0]), "+f"(c[1]), "+f"(c[2]), "+f"(c[3])
        : "r"(a0), "r"(a1), "r"(a2), "r"(a3), "r"(b0), "r"(b1));
}

// ============================================================
// K0_PREP: merged prep (feaT transpose / w_com split / w_dcn split)
// branch by block range; launched as grid 7336 x 256.
// Block layout: [0,6400) feaT, [6400,7048) wA, [7048,7336) wd.
// ============================================================
__global__ __launch_bounds__(256) void k0_prep(
    const float* __restrict__ fea,
    const float* __restrict__ w_com,
    const float* __restrict__ w_dcn)
{
    __shared__ float s[16][65];
    int bid = blockIdx.x;
    int t   = threadIdx.x;

    if (bid < 6400) {
        // ---- feaT: fea NCHW -> NHWC-per-group g_feaT[b][g][p][c16] ----
        int b    = bid / 1600;
        int rem  = bid - b * 1600;
        int g    = rem / 400;
        int base = (rem - g * 400) * 64;
        #pragma unroll
        for (int r = 0; r < 4; r++) {
            int idx = t + r * 256;
            int c = idx >> 6, p = idx & 63;
            s[c][p] = fea[((size_t)(b * C + g * CG + c)) * HW + base + p];
        }
        __syncthreads();
        int p = t >> 2, q = (t & 3) * 4;
        float4 v = make_float4(s[q][p], s[q+1][p], s[q+2][p], s[q+3][p]);
        *(float4*)(g_feaT + (((size_t)(b * DG + g) * HW) + base + p) * CG + q) = v;
    } else if (bid < 7048) {
        // ---- wA: w_com -> bf16 hi/lo [half][part][tap][oc64][72] ----
        int idx = (bid - 6400) * 256 + t;
        if (idx < 2 * 2 * 9 * 64 * 72) {
            int ic = idx % 72;
            int r  = idx / 72;
            int oc = r & 63;
            int r2 = r >> 6;
            int tap = r2 % 9;
            int hp  = r2 / 9;
            int part = hp & 1, half = hp >> 1;
            int ocg = half * 64 + oc;
            float v = (ocg < CO2 && ic < 64)
                    ? w_com[(size_t)ocg * (C * 9) + ic * 9 + tap] : 0.f;
            __nv_bfloat16 h = __float2bfloat16(v);
            __nv_bfloat16 l = __float2bfloat16(v - __bfloat162float(h));
            g_wA[idx] = part ? l : h;
        }
    } else {
        // ---- wd: w_dcn -> bf16 hi/lo [gk 36][part 2][oc 64][k 16] ----
        int idx = (bid - 7048) * 256 + t;
        if (idx < 36 * 2 * 64 * 16) {
            int kk   = idx & 15;
            int oc   = (idx >> 4) & 63;
            int part = (idx >> 10) & 1;
            int gk   = idx >> 11;
            int g = gk / 9, k = gk - 9 * g;
            float v = w_dcn[(size_t)oc * JDIM + (g * CG + kk) * KKTAP + k];
            __nv_bfloat16 h = __float2bfloat16(v);
            __nv_bfloat16 l = __float2bfloat16(v - __bfloat162float(h));
            g_wd[idx] = part ? l : h;
        }
    }
}

// ============================================================
// K1: off_feat = BN(fea @ w_off) -> NHWC bf16 hi/lo (MLP=8)
// ============================================================
__global__ __launch_bounds__(256, 2) void k1_pointwise(
    const float* __restrict__ fea, const float* __restrict__ w_off,
    const float* __restrict__ gamma, const float* __restrict__ beta,
    const float* __restrict__ mean, const float* __restrict__ var)
{
    __shared__ float ws[64 * 64];
    __shared__ float sc[64], sh[64];
    int t = threadIdx.x;
    for (int idx = t; idx < 4096; idx += 256) {
        int o = idx & 63, i = idx >> 6;
        ws[i * 64 + o] = w_off[o * 64 + i];
    }
    if (t < 64) {
        float inv = gamma[t] * rsqrtf(var[t] + 1e-5f);
        sc[t] = inv;
        sh[t] = beta[t] - mean[t] * inv;
    }
    __syncthreads();

    int b = blockIdx.y;
    int p = blockIdx.x * 256 + t;
    const float* fb = fea + (size_t)b * C * HW + p;

    unsigned long long acc[32];
    #pragma unroll
    for (int o = 0; o < 32; o++) acc[o] = 0ull;

    #pragma unroll
    for (int i0 = 0; i0 < 64; i0 += 8) {
        float a[8];
        #pragma unroll
        for (int j = 0; j < 8; j++)
            a[j] = fb[(size_t)(i0 + j) * HW];
        #pragma unroll
        for (int j = 0; j < 8; j++) {
            unsigned long long a2 = pack2(a[j], a[j]);
            const ulonglong2* w2 = (const ulonglong2*)(ws + (i0 + j) * 64);
            #pragma unroll
            for (int o4 = 0; o4 < 16; o4++) {
                ulonglong2 w = w2[o4];
                fma2(acc[2*o4+0], a2, w.x);
                fma2(acc[2*o4+1], a2, w.y);
            }
        }
    }

    uint4* dh = (uint4*)(g_qh + ((size_t)(b * HW) + p) * 64);
    uint4* dl = (uint4*)(g_ql + ((size_t)(b * HW) + p) * 64);
    #pragma unroll
    for (int j = 0; j < 8; j++) {
        unsigned int hv[4], lv[4];
        #pragma unroll
        for (int q = 0; q < 4; q++) {
            int o = 4 * j + q;
            float v0, v1;
            unpack2(acc[o], v0, v1);
            v0 = v0 * sc[2*o]   + sh[2*o];
            v1 = v1 * sc[2*o+1] + sh[2*o+1];
            __nv_bfloat16 h0 = __float2bfloat16(v0);
            __nv_bfloat16 l0 = __float2bfloat16(v0 - __bfloat162float(h0));
            __nv_bfloat16 h1 = __float2bfloat16(v1);
            __nv_bfloat16 l1 = __float2bfloat16(v1 - __bfloat162float(h1));
            hv[q] = (unsigned)__bfloat16_as_ushort(h0) |
                    ((unsigned)__bfloat16_as_ushort(h1) << 16);
            lv[q] = (unsigned)__bfloat16_as_ushort(l0) |
                    ((unsigned)__bfloat16_as_ushort(l1) << 16);
        }
        dh[j] = make_uint4(hv[0], hv[1], hv[2], hv[3]);
        dl[j] = make_uint4(lv[0], lv[1], lv[2], lv[3]);
    }
}

// ============================================================
// K2_MMA: conv3x3 via mma.sync bf16 3-split (unchanged).
// ============================================================
#define K2_A_PART  82944
#define K2_B_OFF   165888
#define K2_B_PART  25920
#define K2_SMEM    217728

__global__ __launch_bounds__(256) void k2_mma(const float* __restrict__ b_com)
{
    extern __shared__ __align__(16) char sm[];
    uint32_t smb = smem_u32(sm);
    int t    = threadIdx.x;
    int lane = t & 31;
    int wid  = t >> 5;
    int half = blockIdx.y;

    {
        const uint4* gA = (const uint4*)g_wA + (size_t)half * 10368;
        for (int i = t; i < 10368; i += 256)
            *(uint4*)(sm + i * 16) = gA[i];
    }

    int wm = wid & 1;
    int wn = wid >> 1;
    int g  = lane >> 2;
    int tt = lane & 3;

    uint32_t arow = (uint32_t)((wm * 32 + (lane & 15)) * 144 + (lane >> 4) * 16);
    int bln  = lane & 7;
    uint32_t bk16 = (uint32_t)(((lane >> 3) & 1) * 16);

    float bias[2][2];
    bool  bval[2][2];
    #pragma unroll
    for (int mf = 0; mf < 2; mf++)
        #pragma unroll
        for (int rh = 0; rh < 2; rh++) {
            int ocg = half * 64 + wm * 32 + mf * 16 + g + rh * 8;
            bval[mf][rh] = (ocg < CO2);
            bias[mf][rh] = bval[mf][rh] ? b_com[ocg] : 0.f;
        }

    for (int u = blockIdx.x; u < 800; u += 148) {
        int b  = u / 200;
        int rr = u - b * 200;
        int tr = rr / 10, tc = rr - tr * 10;
        int row0 = tr * 8, col0 = tc * 16;

        __syncthreads();

        for (int idx = t; idx < 2880; idx += 256) {
            int q    = idx & 7;
            int rest = idx >> 3;
            int part = rest & 1;
            int pxi  = rest >> 1;
            int hr = pxi / 18, hc = pxi - hr * 18;
            int grw = row0 + hr - 1, gcw = col0 + hc - 1;
            uint4 v = make_uint4(0u, 0u, 0u, 0u);
            if ((unsigned)grw < (unsigned)H && (unsigned)gcw < (unsigned)W) {
                const __nv_bfloat16* srcb = part ? g_ql : g_qh;
                v = ((const uint4*)(srcb +
                      ((size_t)b * HW + (size_t)grw * W + gcw) * 64))[q];
            }
            *(uint4*)(sm + K2_B_OFF + part * K2_B_PART + pxi * 144 + q * 16) = v;
        }
        __syncthreads();

        float acc[2][4][4];
        #pragma unroll
        for (int mf = 0; mf < 2; mf++)
            #pragma unroll
            for (int nf = 0; nf < 4; nf++)
                #pragma unroll
                for (int i = 0; i < 4; i++) acc[mf][nf][i] = 0.f;

        #pragma unroll 1
        for (int tap = 0; tap < 9; tap++) {
            int dy = tap / 3 - 1;
            int dx = tap - (tap / 3) * 3 - 1;
            uint32_t aA = smb + (uint32_t)tap * 9216 + arow;
            int brow_base = (2 * wn + dy + 1) * 18 + (dx + 1) + bln;
            uint32_t bB = smb + K2_B_OFF + bk16;

            #pragma unroll
            for (int ks = 0; ks < 4; ks++) {
                uint32_t ah[2][4], al[2][4];
                #pragma unroll
                for (int mf = 0; mf < 2; mf++) {
                    uint32_t ao = aA + (uint32_t)(mf * 2304 + ks * 32);
                    ldsm_x4(ah[mf][0], ah[mf][1], ah[mf][2], ah[mf][3], ao);
                    ldsm_x4(al[mf][0], al[mf][1], al[mf][2], al[mf][3],
                            ao + K2_A_PART);
                }
                #pragma unroll
                for (int nf = 0; nf < 4; nf++) {
                    int pxrow = brow_base + (nf >> 1) * 18 + (nf & 1) * 8;
                    uint32_t baddr = bB + (uint32_t)(pxrow * 144 + ks * 32);
                    uint32_t bh0, bh1, bl0, bl1;
                    ldsm_x2(bh0, bh1, baddr);
                    ldsm_x2(bl0, bl1, baddr + K2_B_PART);
                    #pragma unroll
                    for (int mf = 0; mf < 2; mf++) {
                        mma16816(acc[mf][nf], ah[mf][0], ah[mf][1], ah[mf][2],
                                 ah[mf][3], bh0, bh1);
                        mma16816(acc[mf][nf], ah[mf][0], ah[mf][1], ah[mf][2],
                                 ah[mf][3], bl0, bl1);
                        mma16816(acc[mf][nf], al[mf][0], al[mf][1], al[mf][2],
                                 al[mf][3], bh0, bh1);
                    }
                }
            }
        }

        #pragma unroll
        for (int mf = 0; mf < 2; mf++) {
            int oc0 = half * 64 + wm * 32 + mf * 16 + g;
            #pragma unroll
            for (int nf = 0; nf < 4; nf++) {
                int srow = row0 + 2 * wn + (nf >> 1);
                int scol = col0 + (nf & 1) * 8 + 2 * tt;
                size_t pbase = (size_t)srow * W + scol;
                if (bval[mf][0]) {
                    float* d = g_com + ((size_t)b * CO2 + oc0) * HW + pbase;
                    d[0] = acc[mf][nf][0] + bias[mf][0];
                    d[1] = acc[mf][nf][1] + bias[mf][0];
                }
                if (bval[mf][1]) {
                    float* d = g_com + ((size_t)b * CO2 + oc0 + 8) * HW + pbase;
                    d[0] = acc[mf][nf][2] + bias[mf][1];
                    d[1] = acc[mf][nf][3] + bias[mf][1];
                }
            }
        }
    }
}

// ============================================================
// K34_MMA: fused sampling + DCN GEMM + relu + residual.
// R13 configuration (best measured).
// ============================================================
__global__ __launch_bounds__(256) void k34_mma(
    const float* __restrict__ fea, const float* __restrict__ b_dcn,
    float* __restrict__ out)
{
    __shared__ __align__(16) char a_sm[2][2][64 * 48];    // [buf][part]
    __shared__ __align__(16) char b_sm[2][2][128 * 48];   // [buf][part]

    int t    = threadIdx.x;
    int lane = t & 31;
    int wid  = t >> 5;
    int b    = blockIdx.y;
    int n0   = blockIdx.x * NT;

    const float* comb = g_com  + (size_t)b * CO2 * HW;
    const float* ftb  = g_feaT + (size_t)b * DG * HW * CG;

    int pxi   = t & 127;
    int layer = t >> 7;
    int c0    = layer * 8;
    int p     = n0 + pxi;
    int ph    = p / W;
    int pw    = p - ph * W;

    int aw_part = t >> 7;
    int aw_row  = (t >> 1) & 63;
    int aw_half = t & 1;

    int wm = wid & 1;
    int wn = wid >> 1;
    int g  = lane >> 2;
    int tt = lane & 3;
    uint32_t a_lane = (uint32_t)((wm * 32 + (lane & 15)) * 48 + (lane >> 4) * 16);
    uint32_t b_lane = (uint32_t)((lane & 7) * 48 + ((lane >> 3) & 1) * 16);

    uint32_t ab[2][2], bb[2][2];
    #pragma unroll
    for (int bu = 0; bu < 2; bu++)
        #pragma unroll
        for (int pa = 0; pa < 2; pa++) {
            ab[bu][pa] = smem_u32(&a_sm[bu][pa][0]);
            bb[bu][pa] = smem_u32(&b_sm[bu][pa][0]);
        }

    float acc[2][4][4];
    #pragma unroll
    for (int mf = 0; mf < 2; mf++)
        #pragma unroll
        for (int nf = 0; nf < 4; nf++)
            #pragma unroll
            for (int i = 0; i < 4; i++) acc[mf][nf][i] = 0.f;

// all internals _-prefixed (macro-arg collision hazard).
#define PRODUCE(GK, BUF)                                                      \
    {                                                                         \
        int _gk = (GK);                                                       \
        int _buf = (BUF);                                                     \
        int _g = _gk / 9, _k = _gk - 9 * _g;                                  \
        float _dy = comb[(size_t)(_g*18 + 2*_k    ) * HW + p];                \
        float _dx = comb[(size_t)(_g*18 + 2*_k + 1) * HW + p];                \
        float _mm = comb[(size_t)(72 + _g*9 + _k  ) * HW + p];                \
        _mm = 1.f / (1.f + __expf(-_mm));                                     \
        float _py = _dy + (float)(_k / 3 - 1) + (float)ph;                    \
        float _px = _dx + (float)(_k % 3 - 1) + (float)pw;                    \
        float _y0f = floorf(_py), _x0f = floorf(_px);                         \
        float _wy = _py - _y0f, _wx = _px - _x0f;                             \
        int _y0 = (int)_y0f, _x0 = (int)_x0f;                                 \
        int _y1 = _y0 + 1,   _x1 = _x0 + 1;                                   \
        bool _vy0 = (_y0 >= 0 && _y0 < H), _vy1 = (_y1 >= 0 && _y1 < H);      \
        bool _vx0 = (_x0 >= 0 && _x0 < W), _vx1 = (_x1 >= 0 && _x1 < W);      \
        float _w00 = (1.f-_wy)*(1.f-_wx) * (float)(_vy0 && _vx0) * _mm;       \
        float _w01 = (1.f-_wy)*_wx       * (float)(_vy0 && _vx1) * _mm;       \
        float _w10 = _wy*(1.f-_wx)       * (float)(_vy1 && _vx0) * _mm;       \
        float _w11 = _wy*_wx             * (float)(_vy1 && _vx1) * _mm;       \
        int _y0c = min(max(_y0, 0), H-1), _y1c = min(max(_y1, 0), H-1);       \
        int _x0c = min(max(_x0, 0), W-1), _x1c = min(max(_x1, 0), W-1);       \
        const float* _fg  = ftb + (size_t)_g * HW * CG;                       \
        const float* _p00 = _fg + (size_t)(_y0c * W + _x0c) * CG + c0;        \
        const float* _p01 = _fg + (size_t)(_y0c * W + _x1c) * CG + c0;        \
        const float* _p10 = _fg + (size_t)(_y1c * W + _x0c) * CG + c0;        \
        const float* _p11 = _fg + (size_t)(_y1c * W + _x1c) * CG + c0;        \
        float4 _a00 = *(const float4*)_p00, _b00 = *(const float4*)(_p00+4);  \
        float4 _a01 = *(const float4*)_p01, _b01 = *(const float4*)(_p01+4);  \
        float4 _a10 = *(const float4*)_p10, _b10 = *(const float4*)(_p10+4);  \
        float4 _a11 = *(const float4*)_p11, _b11 = *(const float4*)(_p11+4);  \
        float _v[8];                                                          \
        _v[0] = _w00*_a00.x+_w01*_a01.x+_w10*_a10.x+_w11*_a11.x;              \
        _v[1] = _w00*_a00.y+_w01*_a01.y+_w10*_a10.y+_w11*_a11.y;              \
        _v[2] = _w00*_a00.z+_w01*_a01.z+_w10*_a10.z+_w11*_a11.z;              \
        _v[3] = _w00*_a00.w+_w01*_a01.w+_w10*_a10.w+_w11*_a11.w;              \
        _v[4] = _w00*_b00.x+_w01*_b01.x+_w10*_b10.x+_w11*_b11.x;              \
        _v[5] = _w00*_b00.y+_w01*_b01.y+_w10*_b10.y+_w11*_b11.y;              \
        _v[6] = _w00*_b00.z+_w01*_b01.z+_w10*_b10.z+_w11*_b11.z;              \
        _v[7] = _w00*_b00.w+_w01*_b01.w+_w10*_b10.w+_w11*_b11.w;              \
        unsigned int _hv[4], _lv[4];                                          \
        _Pragma("unroll")                                                     \
        for (int _q = 0; _q < 4; _q++) {                                      \
            __nv_bfloat16 _h0 = __float2bfloat16(_v[2*_q]);                   \
            __nv_bfloat16 _l0 = __float2bfloat16(_v[2*_q] - __bfloat162float(_h0)); \
            __nv_bfloat16 _h1 = __float2bfloat16(_v[2*_q+1]);                 \
            __nv_bfloat16 _l1 = __float2bfloat16(_v[2*_q+1] - __bfloat162float(_h1)); \
            _hv[_q] = (unsigned)__bfloat16_as_ushort(_h0) |                   \
                      ((unsigned)__bfloat16_as_ushort(_h1) << 16);            \
            _lv[_q] = (unsigned)__bfloat16_as_ushort(_l0) |                   \
                      ((unsigned)__bfloat16_as_ushort(_l1) << 16);            \
        }                                                                     \
        *(uint4*)&b_sm[_buf][0][pxi * 48 + layer * 16] =                      \
            make_uint4(_hv[0], _hv[1], _hv[2], _hv[3]);                       \
        *(uint4*)&b_sm[_buf][1][pxi * 48 + layer * 16] =                      \
            make_uint4(_lv[0], _lv[1], _lv[2], _lv[3]);                       \
        *(uint4*)&a_sm[_buf][aw_part][aw_row * 48 + aw_half * 16] =           \
            *(const uint4*)(g_wd + (((size_t)(_gk * 2 + aw_part) * 64 +       \
                                     aw_row) * 16) + aw_half * 8);            \
    }

    PRODUCE(0, 0)
    __syncthreads();

    for (int gk = 0; gk < 36; gk++) {
        int cur = gk & 1;
        if (gk < 35) PRODUCE(gk + 1, cur ^ 1)

        uint32_t ah[2][4], al[2][4];
        #pragma unroll
        for (int mf = 0; mf < 2; mf++) {
            uint32_t ao = a_lane + (uint32_t)(mf * 16 * 48);
            ldsm_x4(ah[mf][0], ah[mf][1], ah[mf][2], ah[mf][3], ab[cur][0] + ao);
            ldsm_x4(al[mf][0], al[mf][1], al[mf][2], al[mf][3], ab[cur][1] + ao);
        }
        #pragma unroll
        for (int nf = 0; nf < 4; nf++) {
            uint32_t bo = b_lane + (uint32_t)((wn * 32 + nf * 8) * 48);
            uint32_t bh0, bh1, bl0, bl1;
            ldsm_x2(bh0, bh1, bb[cur][0] + bo);
            ldsm_x2(bl0, bl1, bb[cur][1] + bo);
            #pragma unroll
            for (int mf = 0; mf < 2; mf++) {
                mma16816(acc[mf][nf], ah[mf][0], ah[mf][1], ah[mf][2], ah[mf][3],
                         bh0, bh1);
                mma16816(acc[mf][nf], ah[mf][0], ah[mf][1], ah[mf][2], ah[mf][3],
                         bl0, bl1);
                mma16816(acc[mf][nf], al[mf][0], al[mf][1], al[mf][2], al[mf][3],
                         bh0, bh1);
            }
        }
        __syncthreads();
    }
#undef PRODUCE

    // ---- epilogue: bias, relu, residual ----
    #pragma unroll
    for (int mf = 0; mf < 2; mf++) {
        int oc0 = wm * 32 + mf * 16 + g;
        float bi0 = b_dcn[oc0];
        float bi1 = b_dcn[oc0 + 8];
        #pragma unroll
        for (int nf = 0; nf < 4; nf++) {
            int pxl = wn * 32 + nf * 8 + 2 * tt;
            size_t b0 = ((size_t)b * C + oc0) * HW + n0 + pxl;
            size_t b1 = ((size_t)b * C + oc0 + 8) * HW + n0 + pxl;
            float2 f0 = *(const float2*)(fea + b0);
            float2 f1 = *(const float2*)(fea + b1);
            float2 o0, o1;
            o0.x = f0.x + fmaxf(acc[mf][nf][0] + bi0, 0.f);
            o0.y = f0.y + fmaxf(acc[mf][nf][1] + bi0, 0.f);
            o1.x = f1.x + fmaxf(acc[mf][nf][2] + bi1, 0.f);
            o1.y = f1.y + fmaxf(acc[mf][nf][3] + bi1, 0.f);
            *(float2*)(out + b0) = o0;
            *(float2*)(out + b1) = o1;
        }
    }
}

// ============================================================
extern "C" void kernel_launch(void* const* d_in, const int* in_sizes, int n_in,
                              void* d_out, int out_size)
{
    const float* fea      = (const float*)d_in[0];
    const float* w_off    = (const float*)d_in[1];
    const float* bn_gamma = (const float*)d_in[2];
    const float* bn_beta  = (const float*)d_in[3];
    const float* bn_mean  = (const float*)d_in[4];
    const float* bn_var   = (const float*)d_in[5];
    const float* w_com    = (const float*)d_in[6];
    const float* b_com    = (const float*)d_in[7];
    const float* w_dcn    = (const float*)d_in[8];
    const float* b_dcn    = (const float*)d_in[9];
    float* out = (float*)d_out;

    cudaFuncSetAttribute(k2_mma, cudaFuncAttributeMaxDynamicSharedMemorySize, K2_SMEM);

    k0_prep     <<<7336, 256>>>(fea, w_com, w_dcn);
    k1_pointwise<<<dim3(HW/256, BATCH), 256>>>(fea, w_off, bn_gamma, bn_beta, bn_mean, bn_var);
    k2_mma      <<<dim3(148, 2), 256, K2_SMEM>>>(b_com);
    k34_mma     <<<dim3(HW/NT, BATCH), 256>>>(fea, b_dcn, out);
}

// round 16
// speedup vs baseline: 1.2866x; 1.2688x over previous
#include <cuda_runtime.h>
#include <cuda_bf16.h>
#include <cuda_fp16.h>
#include <math.h>
#include <stdint.h>

#define BATCH 4
#define C     64
#define H     160
#define W     160
#define HW    (H*W)
#define DG    4
#define KKTAP 9
#define CG    16
#define CO2   108    // 3*DG*KK
#define JDIM  576    // DG*CG*KK
#define NT    128    // k34 pixel tile

// ---- scratch (no cudaMalloc allowed) ----
__device__ float g_com [BATCH * CO2 * HW];       // 3x3 conv output (fp32)
__device__ __half g_ftH[BATCH * DG * HW * CG];   // fea NHWC-per-group, fp16
__device__ __nv_bfloat16 g_qh [BATCH * HW * 64]; // off_feat NHWC hi
__device__ __nv_bfloat16 g_ql [BATCH * HW * 64]; // off_feat NHWC lo
// w_com A tiles: [half(2)][part(2)][tap(9)][oc(64)][ic 72 padded] bf16
__device__ __nv_bfloat16 g_wA[2 * 2 * 9 * 64 * 72];
// w_dcn A tiles for k34: [chunk 36][part 2][oc 64][k 16] bf16
__device__ __nv_bfloat16 g_wd[36 * 2 * 64 * 16];

// ---------- packed f32x2 helpers ----------
__device__ __forceinline__ unsigned long long pack2(float lo, float hi) {
    unsigned long long r;
    asm("mov.b64 %0, {%1, %2};" : "=l"(r) : "f"(lo), "f"(hi));
    return r;
}
__device__ __forceinline__ void unpack2(unsigned long long v, float& lo, float& hi) {
    asm("mov.b64 {%0, %1}, %2;" : "=f"(lo), "=f"(hi) : "l"(v));
}
__device__ __forceinline__ void fma2(unsigned long long& d,
                                     unsigned long long a,
                                     unsigned long long b) {
    asm("fma.rn.f32x2 %0, %1, %2, %0;" : "+l"(d) : "l"(a), "l"(b));
}

// ---------- mma.sync / ldmatrix helpers ----------
__device__ __forceinline__ uint32_t smem_u32(const void* p) {
    uint32_t a;
    asm("{ .reg .u64 t; cvta.to.shared.u64 t, %1; cvt.u32.u64 %0, t; }"
        : "=r"(a) : "l"(p));
    return a;
}
__device__ __forceinline__ void ldsm_x4(uint32_t& r0, uint32_t& r1,
                                        uint32_t& r2, uint32_t& r3, uint32_t addr) {
    asm volatile("ldmatrix.sync.aligned.m8n8.x4.shared.b16 {%0,%1,%2,%3}, [%4];"
        : "=r"(r0), "=r"(r1), "=r"(r2), "=r"(r3) : "r"(addr));
}
__device__ __forceinline__ void ldsm_x2(uint32_t& r0, uint32_t& r1, uint32_t addr) {
    asm volatile("ldmatrix.sync.aligned.m8n8.x2.shared.b16 {%0,%1}, [%2];"
        : "=r"(r0), "=r"(r1) : "r"(addr));
}
__device__ __forceinline__ void mma16816(float* c,
    uint32_t a0, uint32_t a1, uint32_t a2, uint32_t a3,
    uint32_t b0, uint32_t b1) {
    asm("mma.sync.aligned.m16n8k16.row.col.f32.bf16.bf16.f32 "
        "{%0,%1,%2,%3}, {%4,%5,%6,%7}, {%8,%9}, {%0,%1,%2,%3};"
        : "+f"(c[0]), "+f"(c[1]), "+f"(c[2]), "+f"(c[3])
        : "r"(a0), "r"(a1), "r"(a2), "r"(a3), "r"(b0), "r"(b1));
}

// ============================================================
// K0_PREP: merged prep (feaT fp16 transpose / w_com split / w_dcn split)
// Block layout: [0,6400) feaT, [6400,7048) wA, [7048,7336) wd.
// ============================================================
__global__ __launch_bounds__(256) void k0_prep(
    const float* __restrict__ fea,
    const float* __restrict__ w_com,
    const float* __restrict__ w_dcn)
{
    __shared__ float s[16][65];
    int bid = blockIdx.x;
    int t   = threadIdx.x;

    if (bid < 6400) {
        // ---- feaT: fea NCHW -> NHWC-per-group g_ftH[b][g][p][c16] fp16 ----
        int b    = bid / 1600;
        int rem  = bid - b * 1600;
        int g    = rem / 400;
        int base = (rem - g * 400) * 64;
        #pragma unroll
        for (int r = 0; r < 4; r++) {
            int idx = t + r * 256;
            int c = idx >> 6, p = idx & 63;
            s[c][p] = fea[((size_t)(b * C + g * CG + c)) * HW + base + p];
        }
        __syncthreads();
        int p = t >> 2, q = (t & 3) * 4;
        __half2 h01 = __floats2half2_rn(s[q][p],   s[q+1][p]);
        __half2 h23 = __floats2half2_rn(s[q+2][p], s[q+3][p]);
        uint2 u;
        u.x = *(unsigned int*)&h01;
        u.y = *(unsigned int*)&h23;
        *(uint2*)(g_ftH + (((size_t)(b * DG + g) * HW) + base + p) * CG + q) = u;
    } else if (bid < 7048) {
        // ---- wA: w_com -> bf16 hi/lo [half][part][tap][oc64][72] ----
        int idx = (bid - 6400) * 256 + t;
        if (idx < 2 * 2 * 9 * 64 * 72) {
            int ic = idx % 72;
            int r  = idx / 72;
            int oc = r & 63;
            int r2 = r >> 6;
            int tap = r2 % 9;
            int hp  = r2 / 9;
            int part = hp & 1, half = hp >> 1;
            int ocg = half * 64 + oc;
            float v = (ocg < CO2 && ic < 64)
                    ? w_com[(size_t)ocg * (C * 9) + ic * 9 + tap] : 0.f;
            __nv_bfloat16 h = __float2bfloat16(v);
            __nv_bfloat16 l = __float2bfloat16(v - __bfloat162float(h));
            g_wA[idx] = part ? l : h;
        }
    } else {
        // ---- wd: w_dcn -> bf16 hi/lo [gk 36][part 2][oc 64][k 16] ----
        int idx = (bid - 7048) * 256 + t;
        if (idx < 36 * 2 * 64 * 16) {
            int kk   = idx & 15;
            int oc   = (idx >> 4) & 63;
            int part = (idx >> 10) & 1;
            int gk   = idx >> 11;
            int g = gk / 9, k = gk - 9 * g;
            float v = w_dcn[(size_t)oc * JDIM + (g * CG + kk) * KKTAP + k];
            __nv_bfloat16 h = __float2bfloat16(v);
            __nv_bfloat16 l = __float2bfloat16(v - __bfloat162float(h));
            g_wd[idx] = part ? l : h;
        }
    }
}

// ============================================================
// K1: off_feat = BN(fea @ w_off) -> NHWC bf16 hi/lo (MLP=8)
// ============================================================
__global__ __launch_bounds__(256, 2) void k1_pointwise(
    const float* __restrict__ fea, const float* __restrict__ w_off,
    const float* __restrict__ gamma, const float* __restrict__ beta,
    const float* __restrict__ mean, const float* __restrict__ var)
{
    __shared__ float ws[64 * 64];
    __shared__ float sc[64], sh[64];
    int t = threadIdx.x;
    for (int idx = t; idx < 4096; idx += 256) {
        int o = idx & 63, i = idx >> 6;
        ws[i * 64 + o] = w_off[o * 64 + i];
    }
    if (t < 64) {
        float inv = gamma[t] * rsqrtf(var[t] + 1e-5f);
        sc[t] = inv;
        sh[t] = beta[t] - mean[t] * inv;
    }
    __syncthreads();

    int b = blockIdx.y;
    int p = blockIdx.x * 256 + t;
    const float* fb = fea + (size_t)b * C * HW + p;

    unsigned long long acc[32];
    #pragma unroll
    for (int o = 0; o < 32; o++) acc[o] = 0ull;

    #pragma unroll
    for (int i0 = 0; i0 < 64; i0 += 8) {
        float a[8];
        #pragma unroll
        for (int j = 0; j < 8; j++)
            a[j] = fb[(size_t)(i0 + j) * HW];
        #pragma unroll
        for (int j = 0; j < 8; j++) {
            unsigned long long a2 = pack2(a[j], a[j]);
            const ulonglong2* w2 = (const ulonglong2*)(ws + (i0 + j) * 64);
            #pragma unroll
            for (int o4 = 0; o4 < 16; o4++) {
                ulonglong2 w = w2[o4];
                fma2(acc[2*o4+0], a2, w.x);
                fma2(acc[2*o4+1], a2, w.y);
            }
        }
    }

    uint4* dh = (uint4*)(g_qh + ((size_t)(b * HW) + p) * 64);
    uint4* dl = (uint4*)(g_ql + ((size_t)(b * HW) + p) * 64);
    #pragma unroll
    for (int j = 0; j < 8; j++) {
        unsigned int hv[4], lv[4];
        #pragma unroll
        for (int q = 0; q < 4; q++) {
            int o = 4 * j + q;
            float v0, v1;
            unpack2(acc[o], v0, v1);
            v0 = v0 * sc[2*o]   + sh[2*o];
            v1 = v1 * sc[2*o+1] + sh[2*o+1];
            __nv_bfloat16 h0 = __float2bfloat16(v0);
            __nv_bfloat16 l0 = __float2bfloat16(v0 - __bfloat162float(h0));
            __nv_bfloat16 h1 = __float2bfloat16(v1);
            __nv_bfloat16 l1 = __float2bfloat16(v1 - __bfloat162float(h1));
            hv[q] = (unsigned)__bfloat16_as_ushort(h0) |
                    ((unsigned)__bfloat16_as_ushort(h1) << 16);
            lv[q] = (unsigned)__bfloat16_as_ushort(l0) |
                    ((unsigned)__bfloat16_as_ushort(l1) << 16);
        }
        dh[j] = make_uint4(hv[0], hv[1], hv[2], hv[3]);
        dl[j] = make_uint4(lv[0], lv[1], lv[2], lv[3]);
    }
}

// ============================================================
// K2_MMA: conv3x3 via mma.sync bf16 3-split (unchanged).
// ============================================================
#define K2_A_PART  82944
#define K2_B_OFF   165888
#define K2_B_PART  25920
#define K2_SMEM    217728

__global__ __launch_bounds__(256) void k2_mma(const float* __restrict__ b_com)
{
    extern __shared__ __align__(16) char sm[];
    uint32_t smb = smem_u32(sm);
    int t    = threadIdx.x;
    int lane = t & 31;
    int wid  = t >> 5;
    int half = blockIdx.y;

    {
        const uint4* gA = (const uint4*)g_wA + (size_t)half * 10368;
        for (int i = t; i < 10368; i += 256)
            *(uint4*)(sm + i * 16) = gA[i];
    }

    int wm = wid & 1;
    int wn = wid >> 1;
    int g  = lane >> 2;
    int tt = lane & 3;

    uint32_t arow = (uint32_t)((wm * 32 + (lane & 15)) * 144 + (lane >> 4) * 16);
    int bln  = lane & 7;
    uint32_t bk16 = (uint32_t)(((lane >> 3) & 1) * 16);

    float bias[2][2];
    bool  bval[2][2];
    #pragma unroll
    for (int mf = 0; mf < 2; mf++)
        #pragma unroll
        for (int rh = 0; rh < 2; rh++) {
            int ocg = half * 64 + wm * 32 + mf * 16 + g + rh * 8;
            bval[mf][rh] = (ocg < CO2);
            bias[mf][rh] = bval[mf][rh] ? b_com[ocg] : 0.f;
        }

    for (int u = blockIdx.x; u < 800; u += 148) {
        int b  = u / 200;
        int rr = u - b * 200;
        int tr = rr / 10, tc = rr - tr * 10;
        int row0 = tr * 8, col0 = tc * 16;

        __syncthreads();

        for (int idx = t; idx < 2880; idx += 256) {
            int q    = idx & 7;
            int rest = idx >> 3;
            int part = rest & 1;
            int pxi  = rest >> 1;
            int hr = pxi / 18, hc = pxi - hr * 18;
            int grw = row0 + hr - 1, gcw = col0 + hc - 1;
            uint4 v = make_uint4(0u, 0u, 0u, 0u);
            if ((unsigned)grw < (unsigned)H && (unsigned)gcw < (unsigned)W) {
                const __nv_bfloat16* srcb = part ? g_ql : g_qh;
                v = ((const uint4*)(srcb +
                      ((size_t)b * HW + (size_t)grw * W + gcw) * 64))[q];
            }
            *(uint4*)(sm + K2_B_OFF + part * K2_B_PART + pxi * 144 + q * 16) = v;
        }
        __syncthreads();

        float acc[2][4][4];
        #pragma unroll
        for (int mf = 0; mf < 2; mf++)
            #pragma unroll
            for (int nf = 0; nf < 4; nf++)
                #pragma unroll
                for (int i = 0; i < 4; i++) acc[mf][nf][i] = 0.f;

        #pragma unroll 1
        for (int tap = 0; tap < 9; tap++) {
            int dy = tap / 3 - 1;
            int dx = tap - (tap / 3) * 3 - 1;
            uint32_t aA = smb + (uint32_t)tap * 9216 + arow;
            int brow_base = (2 * wn + dy + 1) * 18 + (dx + 1) + bln;
            uint32_t bB = smb + K2_B_OFF + bk16;

            #pragma unroll
            for (int ks = 0; ks < 4; ks++) {
                uint32_t ah[2][4], al[2][4];
                #pragma unroll
                for (int mf = 0; mf < 2; mf++) {
                    uint32_t ao = aA + (uint32_t)(mf * 2304 + ks * 32);
                    ldsm_x4(ah[mf][0], ah[mf][1], ah[mf][2], ah[mf][3], ao);
                    ldsm_x4(al[mf][0], al[mf][1], al[mf][2], al[mf][3],
                            ao + K2_A_PART);
                }
                #pragma unroll
                for (int nf = 0; nf < 4; nf++) {
                    int pxrow = brow_base + (nf >> 1) * 18 + (nf & 1) * 8;
                    uint32_t baddr = bB + (uint32_t)(pxrow * 144 + ks * 32);
                    uint32_t bh0, bh1, bl0, bl1;
                    ldsm_x2(bh0, bh1, baddr);
                    ldsm_x2(bl0, bl1, baddr + K2_B_PART);
                    #pragma unroll
                    for (int mf = 0; mf < 2; mf++) {
                        mma16816(acc[mf][nf], ah[mf][0], ah[mf][1], ah[mf][2],
                                 ah[mf][3], bh0, bh1);
                        mma16816(acc[mf][nf], ah[mf][0], ah[mf][1], ah[mf][2],
                                 ah[mf][3], bl0, bl1);
                        mma16816(acc[mf][nf], al[mf][0], al[mf][1], al[mf][2],
                                 al[mf][3], bh0, bh1);
                    }
                }
            }
        }

        #pragma unroll
        for (int mf = 0; mf < 2; mf++) {
            int oc0 = half * 64 + wm * 32 + mf * 16 + g;
            #pragma unroll
            for (int nf = 0; nf < 4; nf++) {
                int srow = row0 + 2 * wn + (nf >> 1);
                int scol = col0 + (nf & 1) * 8 + 2 * tt;
                size_t pbase = (size_t)srow * W + scol;
                if (bval[mf][0]) {
                    float* d = g_com + ((size_t)b * CO2 + oc0) * HW + pbase;
                    d[0] = acc[mf][nf][0] + bias[mf][0];
                    d[1] = acc[mf][nf][1] + bias[mf][0];
                }
                if (bval[mf][1]) {
                    float* d = g_com + ((size_t)b * CO2 + oc0 + 8) * HW + pbase;
                    d[0] = acc[mf][nf][2] + bias[mf][1];
                    d[1] = acc[mf][nf][3] + bias[mf][1];
                }
            }
        }
    }
}

// ============================================================
// K34_MMA: fused sampling + DCN GEMM + relu + residual.
// fp16 feature gathers: 1 LDG.128 per corner per thread (was 2),
// 32B pixel rows quadruple line sharing -> ~3-4x fewer L1 wavefronts.
// ============================================================
__global__ __launch_bounds__(256) void k34_mma(
    const float* __restrict__ fea, const float* __restrict__ b_dcn,
    float* __restrict__ out)
{
    __shared__ __align__(16) char a_sm[2][2][64 * 48];    // [buf][part]
    __shared__ __align__(16) char b_sm[2][2][128 * 48];   // [buf][part]

    int t    = threadIdx.x;
    int lane = t & 31;
    int wid  = t >> 5;
    int b    = blockIdx.y;
    int n0   = blockIdx.x * NT;

    const float*  comb = g_com + (size_t)b * CO2 * HW;
    const __half* ftH  = g_ftH + (size_t)b * DG * HW * CG;

    int pxi   = t & 127;
    int layer = t >> 7;
    int c0    = layer * 8;
    int p     = n0 + pxi;
    int ph    = p / W;
    int pw    = p - ph * W;

    int aw_part = t >> 7;
    int aw_row  = (t >> 1) & 63;
    int aw_half = t & 1;

    int wm = wid & 1;
    int wn = wid >> 1;
    int g  = lane >> 2;
    int tt = lane & 3;
    uint32_t a_lane = (uint32_t)((wm * 32 + (lane & 15)) * 48 + (lane >> 4) * 16);
    uint32_t b_lane = (uint32_t)((lane & 7) * 48 + ((lane >> 3) & 1) * 16);

    uint32_t ab[2][2], bb[2][2];
    #pragma unroll
    for (int bu = 0; bu < 2; bu++)
        #pragma unroll
        for (int pa = 0; pa < 2; pa++) {
            ab[bu][pa] = smem_u32(&a_sm[bu][pa][0]);
            bb[bu][pa] = smem_u32(&b_sm[bu][pa][0]);
        }

    float acc[2][4][4];
    #pragma unroll
    for (int mf = 0; mf < 2; mf++)
        #pragma unroll
        for (int nf = 0; nf < 4; nf++)
            #pragma unroll
            for (int i = 0; i < 4; i++) acc[mf][nf][i] = 0.f;

// all internals _-prefixed (macro-arg collision hazard).
#define PRODUCE(GK, BUF)                                                      \
    {                                                                         \
        int _gk = (GK);                                                       \
        int _buf = (BUF);                                                     \
        int _g = _gk / 9, _k = _gk - 9 * _g;                                  \
        float _dy = comb[(size_t)(_g*18 + 2*_k    ) * HW + p];                \
        float _dx = comb[(size_t)(_g*18 + 2*_k + 1) * HW + p];                \
        float _mm = comb[(size_t)(72 + _g*9 + _k  ) * HW + p];                \
        _mm = 1.f / (1.f + __expf(-_mm));                                     \
        float _py = _dy + (float)(_k / 3 - 1) + (float)ph;                    \
        float _px = _dx + (float)(_k % 3 - 1) + (float)pw;                    \
        float _y0f = floorf(_py), _x0f = floorf(_px);                         \
        float _wy = _py - _y0f, _wx = _px - _x0f;                             \
        int _y0 = (int)_y0f, _x0 = (int)_x0f;                                 \
        int _y1 = _y0 + 1,   _x1 = _x0 + 1;                                   \
        bool _vy0 = (_y0 >= 0 && _y0 < H), _vy1 = (_y1 >= 0 && _y1 < H);      \
        bool _vx0 = (_x0 >= 0 && _x0 < W), _vx1 = (_x1 >= 0 && _x1 < W);      \
        float _w00 = (1.f-_wy)*(1.f-_wx) * (float)(_vy0 && _vx0) * _mm;       \
        float _w01 = (1.f-_wy)*_wx       * (float)(_vy0 && _vx1) * _mm;       \
        float _w10 = _wy*(1.f-_wx)       * (float)(_vy1 && _vx0) * _mm;       \
        float _w11 = _wy*_wx             * (float)(_vy1 && _vx1) * _mm;       \
        int _y0c = min(max(_y0, 0), H-1), _y1c = min(max(_y1, 0), H-1);       \
        int _x0c = min(max(_x0, 0), W-1), _x1c = min(max(_x1, 0), W-1);       \
        const __half* _fg = ftH + (size_t)_g * HW * CG;                       \
        uint4 _u00 = *(const uint4*)(_fg + (size_t)(_y0c * W + _x0c) * CG + c0); \
        uint4 _u01 = *(const uint4*)(_fg + (size_t)(_y0c * W + _x1c) * CG + c0); \
        uint4 _u10 = *(const uint4*)(_fg + (size_t)(_y1c * W + _x0c) * CG + c0); \
        uint4 _u11 = *(const uint4*)(_fg + (size_t)(_y1c * W + _x1c) * CG + c0); \
        const __half2* _h00 = (const __half2*)&_u00;                          \
        const __half2* _h01 = (const __half2*)&_u01;                          \
        const __half2* _h10 = (const __half2*)&_u10;                          \
        const __half2* _h11 = (const __half2*)&_u11;                          \
        float _v[8];                                                          \
        _Pragma("unroll")                                                     \
        for (int _j = 0; _j < 4; _j++) {                                      \
            float2 _f00 = __half22float2(_h00[_j]);                           \
            float2 _f01 = __half22float2(_h01[_j]);                           \
            float2 _f10 = __half22float2(_h10[_j]);                           \
            float2 _f11 = __half22float2(_h11[_j]);                           \
            _v[2*_j]   = _w00*_f00.x + _w01*_f01.x + _w10*_f10.x + _w11*_f11.x; \
            _v[2*_j+1] = _w00*_f00.y + _w01*_f01.y + _w10*_f10.y + _w11*_f11.y; \
        }                                                                     \
        unsigned int _hv[4], _lv[4];                                          \
        _Pragma("unroll")                                                     \
        for (int _q = 0; _q < 4; _q++) {                                      \
            __nv_bfloat16 _h0 = __float2bfloat16(_v[2*_q]);                   \
            __nv_bfloat16 _l0 = __float2bfloat16(_v[2*_q] - __bfloat162float(_h0)); \
            __nv_bfloat16 _h1 = __float2bfloat16(_v[2*_q+1]);                 \
            __nv_bfloat16 _l1 = __float2bfloat16(_v[2*_q+1] - __bfloat162float(_h1)); \
            _hv[_q] = (unsigned)__bfloat16_as_ushort(_h0) |                   \
                      ((unsigned)__bfloat16_as_ushort(_h1) << 16);            \
            _lv[_q] = (unsigned)__bfloat16_as_ushort(_l0) |                   \
                      ((unsigned)__bfloat16_as_ushort(_l1) << 16);            \
        }                                                                     \
        *(uint4*)&b_sm[_buf][0][pxi * 48 + layer * 16] =                      \
            make_uint4(_hv[0], _hv[1], _hv[2], _hv[3]);                       \
        *(uint4*)&b_sm[_buf][1][pxi * 48 + layer * 16] =                      \
            make_uint4(_lv[0], _lv[1], _lv[2], _lv[3]);                       \
        *(uint4*)&a_sm[_buf][aw_part][aw_row * 48 + aw_half * 16] =           \
            *(const uint4*)(g_wd + (((size_t)(_gk * 2 + aw_part) * 64 +       \
                                     aw_row) * 16) + aw_half * 8);            \
    }

    PRODUCE(0, 0)
    __syncthreads();

    for (int gk = 0; gk < 36; gk++) {
        int cur = gk & 1;
        if (gk < 35) PRODUCE(gk + 1, cur ^ 1)

        uint32_t ah[2][4], al[2][4];
        #pragma unroll
        for (int mf = 0; mf < 2; mf++) {
            uint32_t ao = a_lane + (uint32_t)(mf * 16 * 48);
            ldsm_x4(ah[mf][0], ah[mf][1], ah[mf][2], ah[mf][3], ab[cur][0] + ao);
            ldsm_x4(al[mf][0], al[mf][1], al[mf][2], al[mf][3], ab[cur][1] + ao);
        }
        #pragma unroll
        for (int nf = 0; nf < 4; nf++) {
            uint32_t bo = b_lane + (uint32_t)((wn * 32 + nf * 8) * 48);
            uint32_t bh0, bh1, bl0, bl1;
            ldsm_x2(bh0, bh1, bb[cur][0] + bo);
            ldsm_x2(bl0, bl1, bb[cur][1] + bo);
            #pragma unroll
            for (int mf = 0; mf < 2; mf++) {
                mma16816(acc[mf][nf], ah[mf][0], ah[mf][1], ah[mf][2], ah[mf][3],
                         bh0, bh1);
                mma16816(acc[mf][nf], ah[mf][0], ah[mf][1], ah[mf][2], ah[mf][3],
                         bl0, bl1);
                mma16816(acc[mf][nf], al[mf][0], al[mf][1], al[mf][2], al[mf][3],
                         bh0, bh1);
            }
        }
        __syncthreads();
    }
#undef PRODUCE

    // ---- epilogue: bias, relu, residual ----
    #pragma unroll
    for (int mf = 0; mf < 2; mf++) {
        int oc0 = wm * 32 + mf * 16 + g;
        float bi0 = b_dcn[oc0];
        float bi1 = b_dcn[oc0 + 8];
        #pragma unroll
        for (int nf = 0; nf < 4; nf++) {
            int pxl = wn * 32 + nf * 8 + 2 * tt;
            size_t b0 = ((size_t)b * C + oc0) * HW + n0 + pxl;
            size_t b1 = ((size_t)b * C + oc0 + 8) * HW + n0 + pxl;
            float2 f0 = *(const float2*)(fea + b0);
            float2 f1 = *(const float2*)(fea + b1);
            float2 o0, o1;
            o0.x = f0.x + fmaxf(acc[mf][nf][0] + bi0, 0.f);
            o0.y = f0.y + fmaxf(acc[mf][nf][1] + bi0, 0.f);
            o1.x = f1.x + fmaxf(acc[mf][nf][2] + bi1, 0.f);
            o1.y = f1.y + fmaxf(acc[mf][nf][3] + bi1, 0.f);
            *(float2*)(out + b0) = o0;
            *(float2*)(out + b1) = o1;
        }
    }
}

// ============================================================
extern "C" void kernel_launch(void* const* d_in, const int* in_sizes, int n_in,
                              void* d_out, int out_size)
{
    const float* fea      = (const float*)d_in[0];
    const float* w_off    = (const float*)d_in[1];
    const float* bn_gamma = (const float*)d_in[2];
    const float* bn_beta  = (const float*)d_in[3];
    const float* bn_mean  = (const float*)d_in[4];
    const float* bn_var   = (const float*)d_in[5];
    const float* w_com    = (const float*)d_in[6];
    const float* b_com    = (const float*)d_in[7];
    const float* w_dcn    = (const float*)d_in[8];
    const float* b_dcn    = (const float*)d_in[9];
    float* out = (float*)d_out;

    cudaFuncSetAttribute(k2_mma, cudaFuncAttributeMaxDynamicSharedMemorySize, K2_SMEM);

    k0_prep     <<<7336, 256>>>(fea, w_com, w_dcn);
    k1_pointwise<<<dim3(HW/256, BATCH), 256>>>(fea, w_off, bn_gamma, bn_beta, bn_mean, bn_var);
    k2_mma      <<<dim3(148, 2), 256, K2_SMEM>>>(b_com);
    k34_mma     <<<dim3(HW/NT, BATCH), 256>>>(fea, b_dcn, out);
}

// round 17
// speedup vs baseline: 1.6419x; 1.2761x over previous
#include <cuda_runtime.h>
#include <cuda_bf16.h>
#include <cuda_fp16.h>
#include <math.h>
#include <stdint.h>

#define BATCH 4
#define C     64
#define H     160
#define W     160
#define HW    (H*W)
#define DG    4
#define KKTAP 9
#define CG    16
#define CO2   108    // 3*DG*KK
#define JDIM  576    // DG*CG*KK
#define NT    128    // k34 pixel tile

// ---- scratch (no cudaMalloc allowed) ----
__device__ float g_com [BATCH * CO2 * HW];       // 3x3 conv output (fp32)
__device__ __half g_ftH[BATCH * DG * HW * CG];   // fea NHWC-per-group, fp16
__device__ __nv_bfloat16 g_qh [BATCH * HW * 64]; // off_feat NHWC bf16
// w_com A tiles (hi only): [half(2)][tap(9)][oc(64)][ic 72 padded] bf16
__device__ __nv_bfloat16 g_wA[2 * 9 * 64 * 72];
// w_dcn A tiles for k34: [chunk 36][part 2][oc 64][k 16] bf16
__device__ __nv_bfloat16 g_wd[36 * 2 * 64 * 16];

// ---------- packed f32x2 helpers ----------
__device__ __forceinline__ unsigned long long pack2(float lo, float hi) {
    unsigned long long r;
    asm("mov.b64 %0, {%1, %2};" : "=l"(r) : "f"(lo), "f"(hi));
    return r;
}
__device__ __forceinline__ void unpack2(unsigned long long v, float& lo, float& hi) {
    asm("mov.b64 {%0, %1}, %2;" : "=f"(lo), "=f"(hi) : "l"(v));
}
__device__ __forceinline__ void fma2(unsigned long long& d,
                                     unsigned long long a,
                                     unsigned long long b) {
    asm("fma.rn.f32x2 %0, %1, %2, %0;" : "+l"(d) : "l"(a), "l"(b));
}

// ---------- mma.sync / ldmatrix helpers ----------
__device__ __forceinline__ uint32_t smem_u32(const void* p) {
    uint32_t a;
    asm("{ .reg .u64 t; cvta.to.shared.u64 t, %1; cvt.u32.u64 %0, t; }"
        : "=r"(a) : "l"(p));
    return a;
}
__device__ __forceinline__ void ldsm_x4(uint32_t& r0, uint32_t& r1,
                                        uint32_t& r2, uint32_t& r3, uint32_t addr) {
    asm volatile("ldmatrix.sync.aligned.m8n8.x4.shared.b16 {%0,%1,%2,%3}, [%4];"
        : "=r"(r0), "=r"(r1), "=r"(r2), "=r"(r3) : "r"(addr));
}
__device__ __forceinline__ void ldsm_x2(uint32_t& r0, uint32_t& r1, uint32_t addr) {
    asm volatile("ldmatrix.sync.aligned.m8n8.x2.shared.b16 {%0,%1}, [%2];"
        : "=r"(r0), "=r"(r1) : "r"(addr));
}
__device__ __forceinline__ void mma16816(float* c,
    uint32_t a0, uint32_t a1, uint32_t a2, uint32_t a3,
    uint32_t b0, uint32_t b1) {
    asm("mma.sync.aligned.m16n8k16.row.col.f32.bf16.bf16.f32 "
        "{%0,%1,%2,%3}, {%4,%5,%6,%7}, {%8,%9}, {%0,%1,%2,%3};"
        : "+f"(c[0]), "+f"(c[1]), "+f"(c[2]), "+f"(c[3])
        : "r"(a0), "r"(a1), "r"(a2), "r"(a3), "r"(b0), "r"(b1));
}

// ============================================================
// K0_PREP: merged prep.
// Block layout: [0,6400) feaT fp16, [6400,6724) wA hi, [6724,7012) wd.
// ============================================================
__global__ __launch_bounds__(256) void k0_prep(
    const float* __restrict__ fea,
    const float* __restrict__ w_com,
    const float* __restrict__ w_dcn)
{
    __shared__ float s[16][65];
    int bid = blockIdx.x;
    int t   = threadIdx.x;

    if (bid < 6400) {
        // ---- feaT: fea NCHW -> NHWC-per-group g_ftH[b][g][p][c16] fp16 ----
        int b    = bid / 1600;
        int rem  = bid - b * 1600;
        int g    = rem / 400;
        int base = (rem - g * 400) * 64;
        #pragma unroll
        for (int r = 0; r < 4; r++) {
            int idx = t + r * 256;
            int c = idx >> 6, p = idx & 63;
            s[c][p] = fea[((size_t)(b * C + g * CG + c)) * HW + base + p];
        }
        __syncthreads();
        int p = t >> 2, q = (t & 3) * 4;
        __half2 h01 = __floats2half2_rn(s[q][p],   s[q+1][p]);
        __half2 h23 = __floats2half2_rn(s[q+2][p], s[q+3][p]);
        uint2 u;
        u.x = *(unsigned int*)&h01;
        u.y = *(unsigned int*)&h23;
        *(uint2*)(g_ftH + (((size_t)(b * DG + g) * HW) + base + p) * CG + q) = u;
    } else if (bid < 6724) {
        // ---- wA (hi only): w_com -> bf16 [half][tap][oc64][72] ----
        int idx = (bid - 6400) * 256 + t;
        if (idx < 2 * 9 * 64 * 72) {
            int ic = idx % 72;
            int r  = idx / 72;
            int oc = r & 63;
            int r2 = r >> 6;            // half*9 + tap
            int tap  = r2 % 9;
            int half = r2 / 9;
            int ocg = half * 64 + oc;
            float v = (ocg < CO2 && ic < 64)
                    ? w_com[(size_t)ocg * (C * 9) + ic * 9 + tap] : 0.f;
            g_wA[idx] = __float2bfloat16(v);
        }
    } else {
        // ---- wd: w_dcn -> bf16 hi/lo [gk 36][part 2][oc 64][k 16] ----
        int idx = (bid - 6724) * 256 + t;
        if (idx < 36 * 2 * 64 * 16) {
            int kk   = idx & 15;
            int oc   = (idx >> 4) & 63;
            int part = (idx >> 10) & 1;
            int gk   = idx >> 11;
            int g = gk / 9, k = gk - 9 * g;
            float v = w_dcn[(size_t)oc * JDIM + (g * CG + kk) * KKTAP + k];
            __nv_bfloat16 h = __float2bfloat16(v);
            __nv_bfloat16 l = __float2bfloat16(v - __bfloat162float(h));
            g_wd[idx] = part ? l : h;
        }
    }
}

// ============================================================
// K1: off_feat = BN(fea @ w_off) -> NHWC bf16 (hi only, MLP=8)
// ============================================================
__global__ __launch_bounds__(256, 2) void k1_pointwise(
    const float* __restrict__ fea, const float* __restrict__ w_off,
    const float* __restrict__ gamma, const float* __restrict__ beta,
    const float* __restrict__ mean, const float* __restrict__ var)
{
    __shared__ float ws[64 * 64];
    __shared__ float sc[64], sh[64];
    int t = threadIdx.x;
    for (int idx = t; idx < 4096; idx += 256) {
        int o = idx & 63, i = idx >> 6;
        ws[i * 64 + o] = w_off[o * 64 + i];
    }
    if (t < 64) {
        float inv = gamma[t] * rsqrtf(var[t] + 1e-5f);
        sc[t] = inv;
        sh[t] = beta[t] - mean[t] * inv;
    }
    __syncthreads();

    int b = blockIdx.y;
    int p = blockIdx.x * 256 + t;
    const float* fb = fea + (size_t)b * C * HW + p;

    unsigned long long acc[32];
    #pragma unroll
    for (int o = 0; o < 32; o++) acc[o] = 0ull;

    #pragma unroll
    for (int i0 = 0; i0 < 64; i0 += 8) {
        float a[8];
        #pragma unroll
        for (int j = 0; j < 8; j++)
            a[j] = fb[(size_t)(i0 + j) * HW];
        #pragma unroll
        for (int j = 0; j < 8; j++) {
            unsigned long long a2 = pack2(a[j], a[j]);
            const ulonglong2* w2 = (const ulonglong2*)(ws + (i0 + j) * 64);
            #pragma unroll
            for (int o4 = 0; o4 < 16; o4++) {
                ulonglong2 w = w2[o4];
                fma2(acc[2*o4+0], a2, w.x);
                fma2(acc[2*o4+1], a2, w.y);
            }
        }
    }

    uint4* dh = (uint4*)(g_qh + ((size_t)(b * HW) + p) * 64);
    #pragma unroll
    for (int j = 0; j < 8; j++) {
        unsigned int hv[4];
        #pragma unroll
        for (int q = 0; q < 4; q++) {
            int o = 4 * j + q;
            float v0, v1;
            unpack2(acc[o], v0, v1);
            v0 = v0 * sc[2*o]   + sh[2*o];
            v1 = v1 * sc[2*o+1] + sh[2*o+1];
            __nv_bfloat16 h0 = __float2bfloat16(v0);
            __nv_bfloat16 h1 = __float2bfloat16(v1);
            hv[q] = (unsigned)__bfloat16_as_ushort(h0) |
                    ((unsigned)__bfloat16_as_ushort(h1) << 16);
        }
        dh[j] = make_uint4(hv[0], hv[1], hv[2], hv[3]);
    }
}

// ============================================================
// K2_MMA: conv3x3 via mma.sync, SINGLE bf16 (offset/mask path only
// needs ~2e-4 precision). smem 106 KB -> 2 CTAs/SM, 1 wave.
// ============================================================
#define K2_B_OFF   82944              // A bytes (9*64*144)
#define K2_SMEM    108864             // + B 180*144

__global__ __launch_bounds__(256) void k2_mma(const float* __restrict__ b_com)
{
    extern __shared__ __align__(16) char sm[];
    uint32_t smb = smem_u32(sm);
    int t    = threadIdx.x;
    int lane = t & 31;
    int wid  = t >> 5;
    int half = blockIdx.y;

    {
        const uint4* gA = (const uint4*)g_wA + (size_t)half * 5184;
        for (int i = t; i < 5184; i += 256)
            *(uint4*)(sm + i * 16) = gA[i];
    }

    int wm = wid & 1;
    int wn = wid >> 1;
    int g  = lane >> 2;
    int tt = lane & 3;

    uint32_t arow = (uint32_t)((wm * 32 + (lane & 15)) * 144 + (lane >> 4) * 16);
    int bln  = lane & 7;
    uint32_t bk16 = (uint32_t)(((lane >> 3) & 1) * 16);

    float bias[2][2];
    bool  bval[2][2];
    #pragma unroll
    for (int mf = 0; mf < 2; mf++)
        #pragma unroll
        for (int rh = 0; rh < 2; rh++) {
            int ocg = half * 64 + wm * 32 + mf * 16 + g + rh * 8;
            bval[mf][rh] = (ocg < CO2);
            bias[mf][rh] = bval[mf][rh] ? b_com[ocg] : 0.f;
        }

    for (int u = blockIdx.x; u < 800; u += 148) {
        int b  = u / 200;
        int rr = u - b * 200;
        int tr = rr / 10, tc = rr - tr * 10;
        int row0 = tr * 8, col0 = tc * 16;

        __syncthreads();

        for (int idx = t; idx < 1440; idx += 256) {
            int q   = idx & 7;
            int pxi = idx >> 3;
            int hr = pxi / 18, hc = pxi - hr * 18;
            int grw = row0 + hr - 1, gcw = col0 + hc - 1;
            uint4 v = make_uint4(0u, 0u, 0u, 0u);
            if ((unsigned)grw < (unsigned)H && (unsigned)gcw < (unsigned)W)
                v = ((const uint4*)(g_qh +
                      ((size_t)b * HW + (size_t)grw * W + gcw) * 64))[q];
            *(uint4*)(sm + K2_B_OFF + pxi * 144 + q * 16) = v;
        }
        __syncthreads();

        float acc[2][4][4];
        #pragma unroll
        for (int mf = 0; mf < 2; mf++)
            #pragma unroll
            for (int nf = 0; nf < 4; nf++)
                #pragma unroll
                for (int i = 0; i < 4; i++) acc[mf][nf][i] = 0.f;

        #pragma unroll 1
        for (int tap = 0; tap < 9; tap++) {
            int dy = tap / 3 - 1;
            int dx = tap - (tap / 3) * 3 - 1;
            uint32_t aA = smb + (uint32_t)tap * 9216 + arow;
            int brow_base = (2 * wn + dy + 1) * 18 + (dx + 1) + bln;
            uint32_t bB = smb + K2_B_OFF + bk16;

            #pragma unroll
            for (int ks = 0; ks < 4; ks++) {
                uint32_t ah[2][4];
                #pragma unroll
                for (int mf = 0; mf < 2; mf++) {
                    uint32_t ao = aA + (uint32_t)(mf * 2304 + ks * 32);
                    ldsm_x4(ah[mf][0], ah[mf][1], ah[mf][2], ah[mf][3], ao);
                }
                #pragma unroll
                for (int nf = 0; nf < 4; nf++) {
                    int pxrow = brow_base + (nf >> 1) * 18 + (nf & 1) * 8;
                    uint32_t baddr = bB + (uint32_t)(pxrow * 144 + ks * 32);
                    uint32_t bh0, bh1;
                    ldsm_x2(bh0, bh1, baddr);
                    #pragma unroll
                    for (int mf = 0; mf < 2; mf++)
                        mma16816(acc[mf][nf], ah[mf][0], ah[mf][1], ah[mf][2],
                                 ah[mf][3], bh0, bh1);
                }
            }
        }

        #pragma unroll
        for (int mf = 0; mf < 2; mf++) {
            int oc0 = half * 64 + wm * 32 + mf * 16 + g;
            #pragma unroll
            for (int nf = 0; nf < 4; nf++) {
                int srow = row0 + 2 * wn + (nf >> 1);
                int scol = col0 + (nf & 1) * 8 + 2 * tt;
                size_t pbase = (size_t)srow * W + scol;
                if (bval[mf][0]) {
                    float* d = g_com + ((size_t)b * CO2 + oc0) * HW + pbase;
                    d[0] = acc[mf][nf][0] + bias[mf][0];
                    d[1] = acc[mf][nf][1] + bias[mf][0];
                }
                if (bval[mf][1]) {
                    float* d = g_com + ((size_t)b * CO2 + oc0 + 8) * HW + pbase;
                    d[0] = acc[mf][nf][2] + bias[mf][1];
                    d[1] = acc[mf][nf][3] + bias[mf][1];
                }
            }
        }
    }
}

// ============================================================
// K34_MMA: fused sampling + DCN GEMM + relu + residual.
// fp16 feature gathers + bf16 3-split MMA (unchanged from R16).
// ============================================================
__global__ __launch_bounds__(256) void k34_mma(
    const float* __restrict__ fea, const float* __restrict__ b_dcn,
    float* __restrict__ out)
{
    __shared__ __align__(16) char a_sm[2][2][64 * 48];    // [buf][part]
    __shared__ __align__(16) char b_sm[2][2][128 * 48];   // [buf][part]

    int t    = threadIdx.x;
    int lane = t & 31;
    int wid  = t >> 5;
    int b    = blockIdx.y;
    int n0   = blockIdx.x * NT;

    const float*  comb = g_com + (size_t)b * CO2 * HW;
    const __half* ftH  = g_ftH + (size_t)b * DG * HW * CG;

    int pxi   = t & 127;
    int layer = t >> 7;
    int c0    = layer * 8;
    int p     = n0 + pxi;
    int ph    = p / W;
    int pw    = p - ph * W;

    int aw_part = t >> 7;
    int aw_row  = (t >> 1) & 63;
    int aw_half = t & 1;

    int wm = wid & 1;
    int wn = wid >> 1;
    int g  = lane >> 2;
    int tt = lane & 3;
    uint32_t a_lane = (uint32_t)((wm * 32 + (lane & 15)) * 48 + (lane >> 4) * 16);
    uint32_t b_lane = (uint32_t)((lane & 7) * 48 + ((lane >> 3) & 1) * 16);

    uint32_t ab[2][2], bb[2][2];
    #pragma unroll
    for (int bu = 0; bu < 2; bu++)
        #pragma unroll
        for (int pa = 0; pa < 2; pa++) {
            ab[bu][pa] = smem_u32(&a_sm[bu][pa][0]);
            bb[bu][pa] = smem_u32(&b_sm[bu][pa][0]);
        }

    float acc[2][4][4];
    #pragma unroll
    for (int mf = 0; mf < 2; mf++)
        #pragma unroll
        for (int nf = 0; nf < 4; nf++)
            #pragma unroll
            for (int i = 0; i < 4; i++) acc[mf][nf][i] = 0.f;

// all internals _-prefixed (macro-arg collision hazard).
#define PRODUCE(GK, BUF)                                                      \
    {                                                                         \
        int _gk = (GK);                                                       \
        int _buf = (BUF);                                                     \
        int _g = _gk / 9, _k = _gk - 9 * _g;                                  \
        float _dy = comb[(size_t)(_g*18 + 2*_k    ) * HW + p];                \
        float _dx = comb[(size_t)(_g*18 + 2*_k + 1) * HW + p];                \
        float _mm = comb[(size_t)(72 + _g*9 + _k  ) * HW + p];                \
        _mm = 1.f / (1.f + __expf(-_mm));                                     \
        float _py = _dy + (float)(_k / 3 - 1) + (float)ph;                    \
        float _px = _dx + (float)(_k % 3 - 1) + (float)pw;                    \
        float _y0f = floorf(_py), _x0f = floorf(_px);                         \
        float _wy = _py - _y0f, _wx = _px - _x0f;                             \
        int _y0 = (int)_y0f, _x0 = (int)_x0f;                                 \
        int _y1 = _y0 + 1,   _x1 = _x0 + 1;                                   \
        bool _vy0 = (_y0 >= 0 && _y0 < H), _vy1 = (_y1 >= 0 && _y1 < H);      \
        bool _vx0 = (_x0 >= 0 && _x0 < W), _vx1 = (_x1 >= 0 && _x1 < W);      \
        float _w00 = (1.f-_wy)*(1.f-_wx) * (float)(_vy0 && _vx0) * _mm;       \
        float _w01 = (1.f-_wy)*_wx       * (float)(_vy0 && _vx1) * _mm;       \
        float _w10 = _wy*(1.f-_wx)       * (float)(_vy1 && _vx0) * _mm;       \
        float _w11 = _wy*_wx             * (float)(_vy1 && _vx1) * _mm;       \
        int _y0c = min(max(_y0, 0), H-1), _y1c = min(max(_y1, 0), H-1);       \
        int _x0c = min(max(_x0, 0), W-1), _x1c = min(max(_x1, 0), W-1);       \
        const __half* _fg = ftH + (size_t)_g * HW * CG;                       \
        uint4 _u00 = *(const uint4*)(_fg + (size_t)(_y0c * W + _x0c) * CG + c0); \
        uint4 _u01 = *(const uint4*)(_fg + (size_t)(_y0c * W + _x1c) * CG + c0); \
        uint4 _u10 = *(const uint4*)(_fg + (size_t)(_y1c * W + _x0c) * CG + c0); \
        uint4 _u11 = *(const uint4*)(_fg + (size_t)(_y1c * W + _x1c) * CG + c0); \
        const __half2* _h00 = (const __half2*)&_u00;                          \
        const __half2* _h01 = (const __half2*)&_u01;                          \
        const __half2* _h10 = (const __half2*)&_u10;                          \
        const __half2* _h11 = (const __half2*)&_u11;                          \
        float _v[8];                                                          \
        _Pragma("unroll")                                                     \
        for (int _j = 0; _j < 4; _j++) {                                      \
            float2 _f00 = __half22float2(_h00[_j]);                           \
            float2 _f01 = __half22float2(_h01[_j]);                           \
            float2 _f10 = __half22float2(_h10[_j]);                           \
            float2 _f11 = __half22float2(_h11[_j]);                           \
            _v[2*_j]   = _w00*_f00.x + _w01*_f01.x + _w10*_f10.x + _w11*_f11.x; \
            _v[2*_j+1] = _w00*_f00.y + _w01*_f01.y + _w10*_f10.y + _w11*_f11.y; \
        }                                                                     \
        unsigned int _hv[4], _lv[4];                                          \
        _Pragma("unroll")                                                     \
        for (int _q = 0; _q < 4; _q++) {                                      \
            __nv_bfloat16 _h0 = __float2bfloat16(_v[2*_q]);                   \
            __nv_bfloat16 _l0 = __float2bfloat16(_v[2*_q] - __bfloat162float(_h0)); \
            __nv_bfloat16 _h1 = __float2bfloat16(_v[2*_q+1]);                 \
            __nv_bfloat16 _l1 = __float2bfloat16(_v[2*_q+1] - __bfloat162float(_h1)); \
            _hv[_q] = (unsigned)__bfloat16_as_ushort(_h0) |                   \
                      ((unsigned)__bfloat16_as_ushort(_h1) << 16);            \
            _lv[_q] = (unsigned)__bfloat16_as_ushort(_l0) |                   \
                      ((unsigned)__bfloat16_as_ushort(_l1) << 16);            \
        }                                                                     \
        *(uint4*)&b_sm[_buf][0][pxi * 48 + layer * 16] =                      \
            make_uint4(_hv[0], _hv[1], _hv[2], _hv[3]);                       \
        *(uint4*)&b_sm[_buf][1][pxi * 48 + layer * 16] =                      \
            make_uint4(_lv[0], _lv[1], _lv[2], _lv[3]);                       \
        *(uint4*)&a_sm[_buf][aw_part][aw_row * 48 + aw_half * 16] =           \
            *(const uint4*)(g_wd + (((size_t)(_gk * 2 + aw_part) * 64 +       \
                                     aw_row) * 16) + aw_half * 8);            \
    }

    PRODUCE(0, 0)
    __syncthreads();

    for (int gk = 0; gk < 36; gk++) {
        int cur = gk & 1;
        if (gk < 35) PRODUCE(gk + 1, cur ^ 1)

        uint32_t ah[2][4], al[2][4];
        #pragma unroll
        for (int mf = 0; mf < 2; mf++) {
            uint32_t ao = a_lane + (uint32_t)(mf * 16 * 48);
            ldsm_x4(ah[mf][0], ah[mf][1], ah[mf][2], ah[mf][3], ab[cur][0] + ao);
            ldsm_x4(al[mf][0], al[mf][1], al[mf][2], al[mf][3], ab[cur][1] + ao);
        }
        #pragma unroll
        for (int nf = 0; nf < 4; nf++) {
            uint32_t bo = b_lane + (uint32_t)((wn * 32 + nf * 8) * 48);
            uint32_t bh0, bh1, bl0, bl1;
            ldsm_x2(bh0, bh1, bb[cur][0] + bo);
            ldsm_x2(bl0, bl1, bb[cur][1] + bo);
            #pragma unroll
            for (int mf = 0; mf < 2; mf++) {
                mma16816(acc[mf][nf], ah[mf][0], ah[mf][1], ah[mf][2], ah[mf][3],
                         bh0, bh1);
                mma16816(acc[mf][nf], ah[mf][0], ah[mf][1], ah[mf][2], ah[mf][3],
                         bl0, bl1);
                mma16816(acc[mf][nf], al[mf][0], al[mf][1], al[mf][2], al[mf][3],
                         bh0, bh1);
            }
        }
        __syncthreads();
    }
#undef PRODUCE

    // ---- epilogue: bias, relu, residual ----
    #pragma unroll
    for (int mf = 0; mf < 2; mf++) {
        int oc0 = wm * 32 + mf * 16 + g;
        float bi0 = b_dcn[oc0];
        float bi1 = b_dcn[oc0 + 8];
        #pragma unroll
        for (int nf = 0; nf < 4; nf++) {
            int pxl = wn * 32 + nf * 8 + 2 * tt;
            size_t b0 = ((size_t)b * C + oc0) * HW + n0 + pxl;
            size_t b1 = ((size_t)b * C + oc0 + 8) * HW + n0 + pxl;
            float2 f0 = *(const float2*)(fea + b0);
            float2 f1 = *(const float2*)(fea + b1);
            float2 o0, o1;
            o0.x = f0.x + fmaxf(acc[mf][nf][0] + bi0, 0.f);
            o0.y = f0.y + fmaxf(acc[mf][nf][1] + bi0, 0.f);
            o1.x = f1.x + fmaxf(acc[mf][nf][2] + bi1, 0.f);
            o1.y = f1.y + fmaxf(acc[mf][nf][3] + bi1, 0.f);
            *(float2*)(out + b0) = o0;
            *(float2*)(out + b1) = o1;
        }
    }
}

// ============================================================
extern "C" void kernel_launch(void* const* d_in, const int* in_sizes, int n_in,
                              void* d_out, int out_size)
{
    const float* fea      = (const float*)d_in[0];
    const float* w_off    = (const float*)d_in[1];
    const float* bn_gamma = (const float*)d_in[2];
    const float* bn_beta  = (const float*)d_in[3];
    const float* bn_mean  = (const float*)d_in[4];
    const float* bn_var   = (const float*)d_in[5];
    const float* w_com    = (const float*)d_in[6];
    const float* b_com    = (const float*)d_in[7];
    const float* w_dcn    = (const float*)d_in[8];
    const float* b_dcn    = (const float*)d_in[9];
    float* out = (float*)d_out;

    cudaFuncSetAttribute(k2_mma, cudaFuncAttributeMaxDynamicSharedMemorySize, K2_SMEM);

    k0_prep     <<<7012, 256>>>(fea, w_com, w_dcn);
    k1_pointwise<<<dim3(HW/256, BATCH), 256>>>(fea, w_off, bn_gamma, bn_beta, bn_mean, bn_var);
    k2_mma      <<<dim3(148, 2), 256, K2_SMEM>>>(b_com);
    k34_mma     <<<dim3(HW/NT, BATCH), 256>>>(fea, b_dcn, out);
}